// round 2
// baseline (speedup 1.0000x reference)
#include <cuda_runtime.h>
#include <cstddef>

#define NN   20000
#define EE   160000
#define ETOT (EE + NN)
#define BB   64
#define HID  64
#define FDIM 1024  /* HEADS*NHID = 16*64 */

// ---------------- scratch (device globals; no allocation) ----------------
__device__ __align__(16) float g_xl[(size_t)NN * FDIM];   // 81.9 MB
__device__ __align__(16) float g_xr[(size_t)NN * FDIM];   // 81.9 MB
__device__ __align__(16) float g_h [(size_t)NN * HID];    // 5.1 MB (h1 then h2)
__device__ int   g_cnt [NN];
__device__ int   g_offs[NN + 1];
__device__ int   g_cursor[NN];
__device__ int   g_srcs[ETOT];
__device__ float g_pool[BB * HID];
__device__ int   g_pcnt[BB];

// ---------------- CSR construction ----------------
__global__ void zero_kernel() {
    int i = blockIdx.x * blockDim.x + threadIdx.x;
    if (i < NN) g_cnt[i] = 0;
    if (i < BB * HID) g_pool[i] = 0.f;
    if (i < BB) g_pcnt[i] = 0;
}

__global__ void hist_kernel(const int* __restrict__ ei) {
    int i = blockIdx.x * blockDim.x + threadIdx.x;
    if (i >= ETOT) return;
    int d = (i < EE) ? ei[EE + i] : (i - EE);   // self-loop dst = node id
    atomicAdd(&g_cnt[d], 1);
}

__global__ void scan_kernel() {
    // one block, 1024 threads, 20 elements per thread (20480 >= 20000)
    __shared__ int ps[1024];
    const int CH = 20;
    int tid = threadIdx.x;
    int base = tid * CH;
    int local[CH];
    int s = 0;
    #pragma unroll
    for (int i = 0; i < CH; i++) {
        int idx = base + i;
        int v = (idx < NN) ? g_cnt[idx] : 0;
        local[i] = s;
        s += v;
    }
    ps[tid] = s;
    __syncthreads();
    // Hillis-Steele inclusive scan of per-thread sums
    for (int off = 1; off < 1024; off <<= 1) {
        int v = (tid >= off) ? ps[tid - off] : 0;
        __syncthreads();
        ps[tid] += v;
        __syncthreads();
    }
    int pre = (tid == 0) ? 0 : ps[tid - 1];
    #pragma unroll
    for (int i = 0; i < CH; i++) {
        int idx = base + i;
        if (idx < NN) {
            int o = pre + local[i];
            g_offs[idx] = o;
            g_cursor[idx] = o;
        }
    }
    if (tid == 1023) g_offs[NN] = ps[1023];
}

__global__ void scatter_kernel(const int* __restrict__ ei) {
    int i = blockIdx.x * blockDim.x + threadIdx.x;
    if (i >= ETOT) return;
    int s, d;
    if (i < EE) { s = ei[i]; d = ei[EE + i]; }
    else        { s = d = i - EE; }
    int pos = atomicAdd(&g_cursor[d], 1);
    g_srcs[pos] = s;
}

// ---------------- fused dual GEMM  out{l,r} = A @ W{l,r} + b{l,r} ----------------
// A: [NN, K] row-major, W: [K, 1024] row-major. blockIdx.z selects l/r.
template <int K, bool A_IS_H>
__global__ __launch_bounds__(256) void gemm_kernel(
    const float* __restrict__ Ain,
    const float* __restrict__ Wl, const float* __restrict__ bl,
    const float* __restrict__ Wr, const float* __restrict__ br)
{
    const float* A    = A_IS_H ? g_h : Ain;
    const float* W    = blockIdx.z ? Wr : Wl;
    const float* bias = blockIdx.z ? br : bl;
    float*       out  = blockIdx.z ? g_xr : g_xl;

    __shared__ float As[16][128];
    __shared__ float Ws[16][128];

    int tid = threadIdx.x;
    int tx = tid & 15, ty = tid >> 4;
    int rowBase = blockIdx.x * 128;
    int colBase = blockIdx.y * 128;

    float acc[8][8];
    #pragma unroll
    for (int i = 0; i < 8; i++)
        #pragma unroll
        for (int j = 0; j < 8; j++) acc[i][j] = 0.f;

    for (int k0 = 0; k0 < K; k0 += 16) {
        // A tile: 128 rows x 16 cols, transposed into As[k][m]
        #pragma unroll
        for (int it = 0; it < 2; it++) {
            int idx = tid + it * 256;       // 0..511
            int r = idx >> 2;               // 0..127
            int c4 = (idx & 3) << 2;        // 0,4,8,12
            int row = rowBase + r;
            float4 v = make_float4(0.f, 0.f, 0.f, 0.f);
            if (row < NN)
                v = *reinterpret_cast<const float4*>(A + (size_t)row * K + k0 + c4);
            As[c4 + 0][r] = v.x; As[c4 + 1][r] = v.y;
            As[c4 + 2][r] = v.z; As[c4 + 3][r] = v.w;
        }
        // W tile: 16 rows x 128 cols
        #pragma unroll
        for (int it = 0; it < 2; it++) {
            int idx = tid + it * 256;       // 0..511
            int r = idx >> 5;               // 0..15
            int c4 = (idx & 31) << 2;       // 0..124
            float4 v = *reinterpret_cast<const float4*>(
                W + (size_t)(k0 + r) * FDIM + colBase + c4);
            *reinterpret_cast<float4*>(&Ws[r][c4]) = v;
        }
        __syncthreads();

        #pragma unroll
        for (int kk = 0; kk < 16; kk++) {
            float4 a0 = *reinterpret_cast<const float4*>(&As[kk][ty * 8]);
            float4 a1 = *reinterpret_cast<const float4*>(&As[kk][ty * 8 + 4]);
            float4 w0 = *reinterpret_cast<const float4*>(&Ws[kk][tx * 8]);
            float4 w1 = *reinterpret_cast<const float4*>(&Ws[kk][tx * 8 + 4]);
            float a[8] = {a0.x, a0.y, a0.z, a0.w, a1.x, a1.y, a1.z, a1.w};
            float w[8] = {w0.x, w0.y, w0.z, w0.w, w1.x, w1.y, w1.z, w1.w};
            #pragma unroll
            for (int i = 0; i < 8; i++)
                #pragma unroll
                for (int j = 0; j < 8; j++)
                    acc[i][j] += a[i] * w[j];
        }
        __syncthreads();
    }

    #pragma unroll
    for (int i = 0; i < 8; i++) {
        int row = rowBase + ty * 8 + i;
        if (row >= NN) continue;
        #pragma unroll
        for (int jj = 0; jj < 2; jj++) {
            int col = colBase + tx * 8 + jj * 4;
            float4 v;
            v.x = acc[i][jj * 4 + 0] + bias[col + 0];
            v.y = acc[i][jj * 4 + 1] + bias[col + 1];
            v.z = acc[i][jj * 4 + 2] + bias[col + 2];
            v.w = acc[i][jj * 4 + 3] + bias[col + 3];
            *reinterpret_cast<float4*>(out + (size_t)row * FDIM + col) = v;
        }
    }
}

// ---------------- fused edge logits + online segment softmax + aggregation ----------------
// One warp per dst node. Lane l at iter k holds indices i = k*128 + l*4 + j
// (j=0..3) of the 1024-wide row => head = 2k + (l>=16), channel = 4*(l&15)+j.
// Writes g_h directly (device symbol used in device code only).
__device__ __forceinline__ float lrelu(float v, float s) {
    return v >= 0.f ? v : s * v;
}

__global__ __launch_bounds__(256) void edge_kernel(
    const float* __restrict__ att,   // [16*64]
    const float* __restrict__ bias)  // [64]
{
    int lane = threadIdx.x & 31;
    int warp = threadIdx.x >> 5;
    int n = blockIdx.x * 8 + warp;
    if (n >= NN) return;

    int beg = g_offs[n], end = g_offs[n + 1];

    const float4* xr4  = reinterpret_cast<const float4*>(g_xr) + (size_t)n * 256;
    const float4* att4 = reinterpret_cast<const float4*>(att);

    float4 xrv[8], attv[8];
    #pragma unroll
    for (int k = 0; k < 8; k++) {
        xrv[k]  = xr4[k * 32 + lane];
        attv[k] = att4[k * 32 + lane];
    }

    float m[8], d[8], acc[8][4];
    #pragma unroll
    for (int k = 0; k < 8; k++) {
        m[k] = -1e30f; d[k] = 0.f;
        acc[k][0] = acc[k][1] = acc[k][2] = acc[k][3] = 0.f;
    }

    for (int e = beg; e < end; e++) {
        int s = g_srcs[e];
        const float4* xl4 = reinterpret_cast<const float4*>(g_xl) + (size_t)s * 256;
        float4 xv[8];
        #pragma unroll
        for (int k = 0; k < 8; k++) xv[k] = xl4[k * 32 + lane];

        #pragma unroll
        for (int k = 0; k < 8; k++) {
            float t0 = lrelu(xv[k].x + xrv[k].x, 0.2f);
            float t1 = lrelu(xv[k].y + xrv[k].y, 0.2f);
            float t2 = lrelu(xv[k].z + xrv[k].z, 0.2f);
            float t3 = lrelu(xv[k].w + xrv[k].w, 0.2f);
            float lg = t0 * attv[k].x + t1 * attv[k].y + t2 * attv[k].z + t3 * attv[k].w;
            // reduce within each half-warp (16 lanes of one head)
            lg += __shfl_xor_sync(0xffffffffu, lg, 1);
            lg += __shfl_xor_sync(0xffffffffu, lg, 2);
            lg += __shfl_xor_sync(0xffffffffu, lg, 4);
            lg += __shfl_xor_sync(0xffffffffu, lg, 8);
            // online softmax update
            float nm = fmaxf(m[k], lg);
            float sc = __expf(m[k] - nm);
            float w  = __expf(lg - nm);
            d[k] = d[k] * sc + w;
            m[k] = nm;
            acc[k][0] = acc[k][0] * sc + w * xv[k].x;
            acc[k][1] = acc[k][1] * sc + w * xv[k].y;
            acc[k][2] = acc[k][2] * sc + w * xv[k].z;
            acc[k][3] = acc[k][3] * sc + w * xv[k].w;
        }
    }

    // finalize: alpha-normalize, sum over this lane's 8 heads (same 4 channels each iter)
    float r0 = 0.f, r1 = 0.f, r2 = 0.f, r3 = 0.f;
    #pragma unroll
    for (int k = 0; k < 8; k++) {
        float inv = 1.f / d[k];
        r0 += acc[k][0] * inv;
        r1 += acc[k][1] * inv;
        r2 += acc[k][2] * inv;
        r3 += acc[k][3] * inv;
    }
    // add the other head-parity (lane ^ 16 holds same channels, other 8 heads)
    r0 += __shfl_xor_sync(0xffffffffu, r0, 16);
    r1 += __shfl_xor_sync(0xffffffffu, r1, 16);
    r2 += __shfl_xor_sync(0xffffffffu, r2, 16);
    r3 += __shfl_xor_sync(0xffffffffu, r3, 16);

    if (lane < 16) {
        int c = lane * 4;
        const float inv16 = 1.f / 16.f;
        float4 o;
        o.x = lrelu(r0 * inv16 + bias[c + 0], 0.01f);
        o.y = lrelu(r1 * inv16 + bias[c + 1], 0.01f);
        o.z = lrelu(r2 * inv16 + bias[c + 2], 0.01f);
        o.w = lrelu(r3 * inv16 + bias[c + 3], 0.01f);
        *reinterpret_cast<float4*>(g_h + (size_t)n * HID + c) = o;
    }
}

// ---------------- global mean pool + classifier/variance heads ----------------
__global__ void pool_kernel(const int* __restrict__ batch) {
    int t = blockIdx.x * blockDim.x + threadIdx.x;
    if (t >= NN * 16) return;
    int n = t >> 4, q = t & 15;
    int b = batch[n];
    float4 v = *reinterpret_cast<const float4*>(g_h + (size_t)n * HID + q * 4);
    atomicAdd(&g_pool[b * HID + q * 4 + 0], v.x);
    atomicAdd(&g_pool[b * HID + q * 4 + 1], v.y);
    atomicAdd(&g_pool[b * HID + q * 4 + 2], v.z);
    atomicAdd(&g_pool[b * HID + q * 4 + 3], v.w);
    if (q == 0) atomicAdd(&g_pcnt[b], 1);
}

__global__ void head_kernel(const float* __restrict__ Wc, const float* __restrict__ bc,
                            const float* __restrict__ Wv, const float* __restrict__ bv,
                            float* __restrict__ out) {
    __shared__ float p[HID];
    int b = blockIdx.x, c = threadIdx.x;
    float cnt = fmaxf((float)g_pcnt[b], 1.f);
    p[c] = g_pool[b * HID + c] / cnt;
    __syncthreads();
    if (c < 10) {
        float s = bc[c];
        #pragma unroll 8
        for (int k = 0; k < HID; k++) s += p[k] * Wc[k * 10 + c];
        out[b * 10 + c] = s;                 // logits [64,10]
    } else if (c == 10) {
        float s = bv[0];
        #pragma unroll 8
        for (int k = 0; k < HID; k++) s += p[k] * Wv[k];
        out[BB * 10 + b] = s;                // log_var [64,1] after logits
    }
}

// ---------------- launch ----------------
extern "C" void kernel_launch(void* const* d_in, const int* in_sizes, int n_in,
                              void* d_out, int out_size) {
    const float* x     = (const float*)d_in[0];
    const int*   ei    = (const int*)  d_in[1];
    const int*   batch = (const int*)  d_in[2];
    const float* W1l   = (const float*)d_in[3];
    const float* b1l   = (const float*)d_in[4];
    const float* W1r   = (const float*)d_in[5];
    const float* b1r   = (const float*)d_in[6];
    const float* att1  = (const float*)d_in[7];
    const float* bias1 = (const float*)d_in[8];
    const float* W2l   = (const float*)d_in[9];
    const float* b2l   = (const float*)d_in[10];
    const float* W2r   = (const float*)d_in[11];
    const float* b2r   = (const float*)d_in[12];
    const float* att2  = (const float*)d_in[13];
    const float* bias2 = (const float*)d_in[14];
    const float* Wc    = (const float*)d_in[15];
    const float* bc    = (const float*)d_in[16];
    const float* Wv    = (const float*)d_in[17];
    const float* bv    = (const float*)d_in[18];
    float* out = (float*)d_out;

    // CSR by dst (built once, reused by both layers)
    zero_kernel<<<(NN + 255) / 256, 256>>>();
    hist_kernel<<<(ETOT + 255) / 256, 256>>>(ei);
    scan_kernel<<<1, 1024>>>();
    scatter_kernel<<<(ETOT + 255) / 256, 256>>>(ei);

    dim3 ggrid((NN + 127) / 128, FDIM / 128, 2);

    // layer 1
    gemm_kernel<128, false><<<ggrid, 256>>>(x, W1l, b1l, W1r, b1r);
    edge_kernel<<<(NN + 7) / 8, 256>>>(att1, bias1);

    // layer 2 (reads g_h, overwrites g_xl/g_xr, then g_h)
    gemm_kernel<64, true><<<ggrid, 256>>>(nullptr, W2l, b2l, W2r, b2r);
    edge_kernel<<<(NN + 7) / 8, 256>>>(att2, bias2);

    // pooling + heads
    pool_kernel<<<(NN * 16 + 255) / 256, 256>>>(batch);
    head_kernel<<<BB, HID>>>(Wc, bc, Wv, bv, out);
}

// round 3
// speedup vs baseline: 1.3119x; 1.3119x over previous
#include <cuda_runtime.h>
#include <cstdint>
#include <cstddef>

#define NN   20000
#define EE   160000
#define ETOT (EE + NN)
#define BB   64
#define HID  64
#define FDIM 1024  /* HEADS*NHID = 16*64 */

// ---------------- scratch (device globals; no allocation) ----------------
__device__ __align__(16) float g_xl[(size_t)NN * FDIM];   // 81.9 MB
__device__ __align__(16) float g_xr[(size_t)NN * FDIM];   // 81.9 MB
__device__ __align__(16) float g_h [(size_t)NN * HID];    // 5.1 MB (h1 then h2)
__device__ int   g_cnt [NN];
__device__ int   g_offs[NN + 1];
__device__ int   g_cursor[NN];
__device__ int   g_srcs[ETOT];
__device__ float g_pool[BB * HID];
__device__ int   g_pcnt[BB];

// ---------------- CSR construction ----------------
__global__ void zero_kernel() {
    int i = blockIdx.x * blockDim.x + threadIdx.x;
    if (i < NN) g_cnt[i] = 0;
    if (i < BB * HID) g_pool[i] = 0.f;
    if (i < BB) g_pcnt[i] = 0;
}

__global__ void hist_kernel(const int* __restrict__ ei) {
    int i = blockIdx.x * blockDim.x + threadIdx.x;
    if (i >= ETOT) return;
    int d = (i < EE) ? ei[EE + i] : (i - EE);   // self-loop dst = node id
    atomicAdd(&g_cnt[d], 1);
}

__global__ void scan_kernel() {
    __shared__ int ps[1024];
    const int CH = 20;
    int tid = threadIdx.x;
    int base = tid * CH;
    int local[CH];
    int s = 0;
    #pragma unroll
    for (int i = 0; i < CH; i++) {
        int idx = base + i;
        int v = (idx < NN) ? g_cnt[idx] : 0;
        local[i] = s;
        s += v;
    }
    ps[tid] = s;
    __syncthreads();
    for (int off = 1; off < 1024; off <<= 1) {
        int v = (tid >= off) ? ps[tid - off] : 0;
        __syncthreads();
        ps[tid] += v;
        __syncthreads();
    }
    int pre = (tid == 0) ? 0 : ps[tid - 1];
    #pragma unroll
    for (int i = 0; i < CH; i++) {
        int idx = base + i;
        if (idx < NN) {
            int o = pre + local[i];
            g_offs[idx] = o;
            g_cursor[idx] = o;
        }
    }
    if (tid == 1023) g_offs[NN] = ps[1023];
}

__global__ void scatter_kernel(const int* __restrict__ ei) {
    int i = blockIdx.x * blockDim.x + threadIdx.x;
    if (i >= ETOT) return;
    int s, d;
    if (i < EE) { s = ei[i]; d = ei[EE + i]; }
    else        { s = d = i - EE; }
    int pos = atomicAdd(&g_cursor[d], 1);
    g_srcs[pos] = s;
}

// ---------------- tf32 tensor-core dual GEMM ----------------
// out{l,r}[NN,1024] = A[NN,K] @ W{l,r}[K,1024] + b{l,r}; blockIdx.z selects l/r.
// Block tile 128x128, BK=32, 8 warps each computing 32(M)x64(N) via
// mma.sync.aligned.m16n8k8.row.col.f32.tf32.tf32.f32.

__device__ __forceinline__ uint32_t f2tf(float x) {
    uint32_t r;
    asm("cvt.rna.tf32.f32 %0, %1;" : "=r"(r) : "f"(x));
    return r;
}

template <int K, bool A_IS_H>
__global__ __launch_bounds__(256) void gemm_tc_kernel(
    const float* __restrict__ Ain,
    const float* __restrict__ Wl, const float* __restrict__ bl,
    const float* __restrict__ Wr, const float* __restrict__ br)
{
    const float* A    = A_IS_H ? g_h : Ain;
    const float* W    = blockIdx.z ? Wr : Wl;
    const float* bias = blockIdx.z ? br : bl;
    float*       out  = blockIdx.z ? g_xr : g_xl;

    constexpr int BK  = 32;
    constexpr int LDA = 129;   // As[k][m] (k-major), padded: conflict-free scalar access
    constexpr int LDB = 132;   // Bs[k][n] (k-major), 16B-aligned rows for float4 STS

    __shared__ uint32_t As[BK * LDA];
    __shared__ uint32_t Bs[BK * LDB];

    int tid  = threadIdx.x;
    int lane = tid & 31, warp = tid >> 5;
    int wm = warp >> 1, wn = warp & 1;       // 4 x 2 warp grid
    int gid = lane >> 2, tig = lane & 3;     // mma fragment coords

    int rowBase = blockIdx.x * 128;
    int colBase = blockIdx.y * 128;

    float acc[2][8][4];
    #pragma unroll
    for (int mt = 0; mt < 2; mt++)
        #pragma unroll
        for (int nt = 0; nt < 8; nt++)
            #pragma unroll
            for (int c = 0; c < 4; c++) acc[mt][nt][c] = 0.f;

    for (int k0 = 0; k0 < K; k0 += BK) {
        // ---- A tile: 128 rows x 32 k, transpose into As[k][m] ----
        #pragma unroll
        for (int i = 0; i < 4; i++) {
            int f  = tid + i * 256;          // 0..1023 float4 slots
            int m  = f >> 3;                 // 0..127
            int kk = (f & 7) << 2;           // 0,4,..,28
            int row = rowBase + m;
            float4 v = make_float4(0.f, 0.f, 0.f, 0.f);
            if (row < NN)
                v = *reinterpret_cast<const float4*>(A + (size_t)row * K + k0 + kk);
            As[(kk + 0) * LDA + m] = f2tf(v.x);
            As[(kk + 1) * LDA + m] = f2tf(v.y);
            As[(kk + 2) * LDA + m] = f2tf(v.z);
            As[(kk + 3) * LDA + m] = f2tf(v.w);
        }
        // ---- B tile: 32 k x 128 n ----
        #pragma unroll
        for (int i = 0; i < 4; i++) {
            int f  = tid + i * 256;
            int kk = f >> 5;                 // 0..31
            int n4 = (f & 31) << 2;          // 0..124
            float4 v = *reinterpret_cast<const float4*>(
                W + (size_t)(k0 + kk) * FDIM + colBase + n4);
            uint4 t;
            t.x = f2tf(v.x); t.y = f2tf(v.y); t.z = f2tf(v.z); t.w = f2tf(v.w);
            *reinterpret_cast<uint4*>(&Bs[kk * LDB + n4]) = t;
        }
        __syncthreads();

        #pragma unroll
        for (int ks = 0; ks < BK / 8; ks++) {
            uint32_t a[2][4], b[8][2];
            #pragma unroll
            for (int mt = 0; mt < 2; mt++) {
                int r = wm * 32 + mt * 16 + gid;
                int c = ks * 8 + tig;
                a[mt][0] = As[c * LDA + r];
                a[mt][1] = As[c * LDA + r + 8];
                a[mt][2] = As[(c + 4) * LDA + r];
                a[mt][3] = As[(c + 4) * LDA + r + 8];
            }
            #pragma unroll
            for (int nt = 0; nt < 8; nt++) {
                int c = wn * 64 + nt * 8 + gid;
                int k1 = ks * 8 + tig;
                b[nt][0] = Bs[k1 * LDB + c];
                b[nt][1] = Bs[(k1 + 4) * LDB + c];
            }
            #pragma unroll
            for (int mt = 0; mt < 2; mt++)
                #pragma unroll
                for (int nt = 0; nt < 8; nt++) {
                    asm volatile(
                        "mma.sync.aligned.m16n8k8.row.col.f32.tf32.tf32.f32 "
                        "{%0,%1,%2,%3}, {%4,%5,%6,%7}, {%8,%9}, {%0,%1,%2,%3};"
                        : "+f"(acc[mt][nt][0]), "+f"(acc[mt][nt][1]),
                          "+f"(acc[mt][nt][2]), "+f"(acc[mt][nt][3])
                        : "r"(a[mt][0]), "r"(a[mt][1]), "r"(a[mt][2]), "r"(a[mt][3]),
                          "r"(b[nt][0]), "r"(b[nt][1]));
                }
        }
        __syncthreads();
    }

    // ---- epilogue: bias add, store ----
    #pragma unroll
    for (int mt = 0; mt < 2; mt++) {
        int row0 = rowBase + wm * 32 + mt * 16 + gid;
        int row1 = row0 + 8;
        #pragma unroll
        for (int nt = 0; nt < 8; nt++) {
            int col = colBase + wn * 64 + nt * 8 + tig * 2;
            float bx = bias[col], by = bias[col + 1];
            if (row0 < NN) {
                float2 v0 = make_float2(acc[mt][nt][0] + bx, acc[mt][nt][1] + by);
                *reinterpret_cast<float2*>(out + (size_t)row0 * FDIM + col) = v0;
            }
            if (row1 < NN) {
                float2 v1 = make_float2(acc[mt][nt][2] + bx, acc[mt][nt][3] + by);
                *reinterpret_cast<float2*>(out + (size_t)row1 * FDIM + col) = v1;
            }
        }
    }
}

// ---------------- fused edge logits + online segment softmax + aggregation ----------------
__device__ __forceinline__ float lrelu(float v, float s) {
    return v >= 0.f ? v : s * v;
}

__global__ __launch_bounds__(256) void edge_kernel(
    const float* __restrict__ att,   // [16*64]
    const float* __restrict__ bias)  // [64]
{
    int lane = threadIdx.x & 31;
    int warp = threadIdx.x >> 5;
    int n = blockIdx.x * 8 + warp;
    if (n >= NN) return;

    int beg = g_offs[n], end = g_offs[n + 1];

    const float4* xr4  = reinterpret_cast<const float4*>(g_xr) + (size_t)n * 256;
    const float4* att4 = reinterpret_cast<const float4*>(att);

    float4 xrv[8], attv[8];
    #pragma unroll
    for (int k = 0; k < 8; k++) {
        xrv[k]  = xr4[k * 32 + lane];
        attv[k] = att4[k * 32 + lane];
    }

    float m[8], d[8], acc[8][4];
    #pragma unroll
    for (int k = 0; k < 8; k++) {
        m[k] = -1e30f; d[k] = 0.f;
        acc[k][0] = acc[k][1] = acc[k][2] = acc[k][3] = 0.f;
    }

    for (int e = beg; e < end; e++) {
        int s = g_srcs[e];
        const float4* xl4 = reinterpret_cast<const float4*>(g_xl) + (size_t)s * 256;
        float4 xv[8];
        #pragma unroll
        for (int k = 0; k < 8; k++) xv[k] = xl4[k * 32 + lane];

        #pragma unroll
        for (int k = 0; k < 8; k++) {
            float t0 = lrelu(xv[k].x + xrv[k].x, 0.2f);
            float t1 = lrelu(xv[k].y + xrv[k].y, 0.2f);
            float t2 = lrelu(xv[k].z + xrv[k].z, 0.2f);
            float t3 = lrelu(xv[k].w + xrv[k].w, 0.2f);
            float lg = t0 * attv[k].x + t1 * attv[k].y + t2 * attv[k].z + t3 * attv[k].w;
            lg += __shfl_xor_sync(0xffffffffu, lg, 1);
            lg += __shfl_xor_sync(0xffffffffu, lg, 2);
            lg += __shfl_xor_sync(0xffffffffu, lg, 4);
            lg += __shfl_xor_sync(0xffffffffu, lg, 8);
            float nm = fmaxf(m[k], lg);
            float sc = __expf(m[k] - nm);
            float w  = __expf(lg - nm);
            d[k] = d[k] * sc + w;
            m[k] = nm;
            acc[k][0] = acc[k][0] * sc + w * xv[k].x;
            acc[k][1] = acc[k][1] * sc + w * xv[k].y;
            acc[k][2] = acc[k][2] * sc + w * xv[k].z;
            acc[k][3] = acc[k][3] * sc + w * xv[k].w;
        }
    }

    float r0 = 0.f, r1 = 0.f, r2 = 0.f, r3 = 0.f;
    #pragma unroll
    for (int k = 0; k < 8; k++) {
        float inv = 1.f / d[k];
        r0 += acc[k][0] * inv;
        r1 += acc[k][1] * inv;
        r2 += acc[k][2] * inv;
        r3 += acc[k][3] * inv;
    }
    r0 += __shfl_xor_sync(0xffffffffu, r0, 16);
    r1 += __shfl_xor_sync(0xffffffffu, r1, 16);
    r2 += __shfl_xor_sync(0xffffffffu, r2, 16);
    r3 += __shfl_xor_sync(0xffffffffu, r3, 16);

    if (lane < 16) {
        int c = lane * 4;
        const float inv16 = 1.f / 16.f;
        float4 o;
        o.x = lrelu(r0 * inv16 + bias[c + 0], 0.01f);
        o.y = lrelu(r1 * inv16 + bias[c + 1], 0.01f);
        o.z = lrelu(r2 * inv16 + bias[c + 2], 0.01f);
        o.w = lrelu(r3 * inv16 + bias[c + 3], 0.01f);
        *reinterpret_cast<float4*>(g_h + (size_t)n * HID + c) = o;
    }
}

// ---------------- global mean pool + classifier/variance heads ----------------
__global__ void pool_kernel(const int* __restrict__ batch) {
    int t = blockIdx.x * blockDim.x + threadIdx.x;
    if (t >= NN * 16) return;
    int n = t >> 4, q = t & 15;
    int b = batch[n];
    float4 v = *reinterpret_cast<const float4*>(g_h + (size_t)n * HID + q * 4);
    atomicAdd(&g_pool[b * HID + q * 4 + 0], v.x);
    atomicAdd(&g_pool[b * HID + q * 4 + 1], v.y);
    atomicAdd(&g_pool[b * HID + q * 4 + 2], v.z);
    atomicAdd(&g_pool[b * HID + q * 4 + 3], v.w);
    if (q == 0) atomicAdd(&g_pcnt[b], 1);
}

__global__ void head_kernel(const float* __restrict__ Wc, const float* __restrict__ bc,
                            const float* __restrict__ Wv, const float* __restrict__ bv,
                            float* __restrict__ out) {
    __shared__ float p[HID];
    int b = blockIdx.x, c = threadIdx.x;
    float cnt = fmaxf((float)g_pcnt[b], 1.f);
    p[c] = g_pool[b * HID + c] / cnt;
    __syncthreads();
    if (c < 10) {
        float s = bc[c];
        #pragma unroll 8
        for (int k = 0; k < HID; k++) s += p[k] * Wc[k * 10 + c];
        out[b * 10 + c] = s;                 // logits [64,10]
    } else if (c == 10) {
        float s = bv[0];
        #pragma unroll 8
        for (int k = 0; k < HID; k++) s += p[k] * Wv[k];
        out[BB * 10 + b] = s;                // log_var [64,1] after logits
    }
}

// ---------------- launch ----------------
extern "C" void kernel_launch(void* const* d_in, const int* in_sizes, int n_in,
                              void* d_out, int out_size) {
    const float* x     = (const float*)d_in[0];
    const int*   ei    = (const int*)  d_in[1];
    const int*   batch = (const int*)  d_in[2];
    const float* W1l   = (const float*)d_in[3];
    const float* b1l   = (const float*)d_in[4];
    const float* W1r   = (const float*)d_in[5];
    const float* b1r   = (const float*)d_in[6];
    const float* att1  = (const float*)d_in[7];
    const float* bias1 = (const float*)d_in[8];
    const float* W2l   = (const float*)d_in[9];
    const float* b2l   = (const float*)d_in[10];
    const float* W2r   = (const float*)d_in[11];
    const float* b2r   = (const float*)d_in[12];
    const float* att2  = (const float*)d_in[13];
    const float* bias2 = (const float*)d_in[14];
    const float* Wc    = (const float*)d_in[15];
    const float* bc    = (const float*)d_in[16];
    const float* Wv    = (const float*)d_in[17];
    const float* bv    = (const float*)d_in[18];
    float* out = (float*)d_out;

    // CSR by dst (built once, reused by both layers)
    zero_kernel<<<(NN + 255) / 256, 256>>>();
    hist_kernel<<<(ETOT + 255) / 256, 256>>>(ei);
    scan_kernel<<<1, 1024>>>();
    scatter_kernel<<<(ETOT + 255) / 256, 256>>>(ei);

    dim3 ggrid((NN + 127) / 128, FDIM / 128, 2);

    // layer 1
    gemm_tc_kernel<128, false><<<ggrid, 256>>>(x, W1l, b1l, W1r, b1r);
    edge_kernel<<<(NN + 7) / 8, 256>>>(att1, bias1);

    // layer 2 (reads g_h, overwrites g_xl/g_xr, then g_h)
    gemm_tc_kernel<64, true><<<ggrid, 256>>>(nullptr, W2l, b2l, W2r, b2r);
    edge_kernel<<<(NN + 7) / 8, 256>>>(att2, bias2);

    // pooling + heads
    pool_kernel<<<(NN * 16 + 255) / 256, 256>>>(batch);
    head_kernel<<<BB, HID>>>(Wc, bc, Wv, bv, out);
}

// round 5
// speedup vs baseline: 1.4179x; 1.0809x over previous
#include <cuda_runtime.h>
#include <cstdint>
#include <cstddef>

#define NN   20000
#define EE   160000
#define ETOT (EE + NN)
#define BB   64
#define HID  64
#define FDIM 1024  /* HEADS*NHID = 16*64 */

// ---------------- scratch (device globals; no allocation) ----------------
__device__ __align__(16) float g_xl[(size_t)NN * FDIM];   // 81.9 MB
__device__ __align__(16) float g_xr[(size_t)NN * FDIM];   // 81.9 MB
__device__ __align__(16) float g_h [(size_t)NN * HID];    // 5.1 MB (h1 then h2)
__device__ int   g_cnt [NN];
__device__ int   g_offs[NN + 1];
__device__ int   g_cursor[NN];
__device__ int   g_srcs[ETOT];
__device__ float g_pool[BB * HID];
__device__ int   g_pcnt[BB];

// ---------------- CSR construction ----------------
__global__ void zero_kernel() {
    int i = blockIdx.x * blockDim.x + threadIdx.x;
    if (i < NN) g_cnt[i] = 0;
    if (i < BB * HID) g_pool[i] = 0.f;
    if (i < BB) g_pcnt[i] = 0;
}

__global__ void hist_kernel(const int* __restrict__ ei) {
    int i = blockIdx.x * blockDim.x + threadIdx.x;
    if (i >= ETOT) return;
    int d = (i < EE) ? ei[EE + i] : (i - EE);   // self-loop dst = node id
    atomicAdd(&g_cnt[d], 1);
}

__global__ void scan_kernel() {
    __shared__ int ps[1024];
    const int CH = 20;
    int tid = threadIdx.x;
    int base = tid * CH;
    int local[CH];
    int s = 0;
    #pragma unroll
    for (int i = 0; i < CH; i++) {
        int idx = base + i;
        int v = (idx < NN) ? g_cnt[idx] : 0;
        local[i] = s;
        s += v;
    }
    ps[tid] = s;
    __syncthreads();
    for (int off = 1; off < 1024; off <<= 1) {
        int v = (tid >= off) ? ps[tid - off] : 0;
        __syncthreads();
        ps[tid] += v;
        __syncthreads();
    }
    int pre = (tid == 0) ? 0 : ps[tid - 1];
    #pragma unroll
    for (int i = 0; i < CH; i++) {
        int idx = base + i;
        if (idx < NN) {
            int o = pre + local[i];
            g_offs[idx] = o;
            g_cursor[idx] = o;
        }
    }
    if (tid == 1023) g_offs[NN] = ps[1023];
}

__global__ void scatter_kernel(const int* __restrict__ ei) {
    int i = blockIdx.x * blockDim.x + threadIdx.x;
    if (i >= ETOT) return;
    int s, d;
    if (i < EE) { s = ei[i]; d = ei[EE + i]; }
    else        { s = d = i - EE; }
    int pos = atomicAdd(&g_cursor[d], 1);
    g_srcs[pos] = s;
}

// ---------------- tf32 tensor-core dual GEMM (cp.async double-buffered) --------
// out{l,r}[NN,1024] = A[NN,K] @ W{l,r}[K,1024] + b{l,r}; blockIdx.z selects l/r.
// Block tile 128x128, BK=16, 2-stage cp.async pipeline. fp32 stored raw in smem;
// cvt.rna.tf32 applied on fragment registers right before the mma (RNA rounding,
// same numerics as converting at store time).

#define CP_ASYNC_CG(dst, src) \
    asm volatile("cp.async.cg.shared.global [%0], [%1], 16;" :: "r"(dst), "l"(src))
#define CP_ASYNC_CG_Z(dst, src, sz) \
    asm volatile("cp.async.cg.shared.global [%0], [%1], 16, %2;" :: "r"(dst), "l"(src), "r"(sz))
#define CP_COMMIT() asm volatile("cp.async.commit_group;")
#define CP_WAIT1()  asm volatile("cp.async.wait_group 1;")
#define CP_WAIT0()  asm volatile("cp.async.wait_group 0;")

__device__ __forceinline__ uint32_t f2tf(float x) {
    uint32_t r;
    asm("cvt.rna.tf32.f32 %0, %1;" : "=r"(r) : "f"(x));
    return r;
}

template <int K, bool A_IS_H>
__global__ __launch_bounds__(256) void gemm_tc_kernel(
    const float* __restrict__ Ain,
    const float* __restrict__ Wl, const float* __restrict__ bl,
    const float* __restrict__ Wr, const float* __restrict__ br)
{
    const float* A    = A_IS_H ? g_h : Ain;
    const float* W    = blockIdx.z ? Wr : Wl;
    const float* bias = blockIdx.z ? br : bl;
    float*       out  = blockIdx.z ? g_xr : g_xl;

    constexpr int BK  = 16;
    constexpr int LDA = 20;    // As[m][k], 80B rows (16B aligned), conflict-free frags
    constexpr int LDB = 132;   // Bs[k][n], 528B rows

    __shared__ float As[2][128 * LDA];
    __shared__ float Bs[2][BK * LDB];

    int tid  = threadIdx.x;
    int lane = tid & 31, warp = tid >> 5;
    int wm = warp >> 1, wn = warp & 1;       // 4 x 2 warp grid
    int gid = lane >> 2, tig = lane & 3;     // mma fragment coords

    int rowBase = blockIdx.x * 128;
    int colBase = blockIdx.y * 128;

    uint32_t sA = (uint32_t)__cvta_generic_to_shared(&As[0][0]);
    uint32_t sB = (uint32_t)__cvta_generic_to_shared(&Bs[0][0]);

    // precomputed per-thread load coordinates
    int a_row0 = tid >> 2,               a_q0 = (tid & 3) << 2;
    int a_row1 = (tid + 256) >> 2,       a_q1 = ((tid + 256) & 3) << 2;
    int b_k0   = tid >> 5,               b_n0 = (tid & 31) << 2;
    int b_k1   = (tid + 256) >> 5,       b_n1 = ((tid + 256) & 31) << 2;
    int rg0 = rowBase + a_row0, rg1 = rowBase + a_row1;
    int sz0 = (rg0 < NN) ? 16 : 0, sz1 = (rg1 < NN) ? 16 : 0;
    const float* a_src0 = A + (size_t)(rg0 < NN ? rg0 : 0) * K + a_q0;
    const float* a_src1 = A + (size_t)(rg1 < NN ? rg1 : 0) * K + a_q1;
    const float* b_src0 = W + (size_t)b_k0 * FDIM + colBase + b_n0;
    const float* b_src1 = W + (size_t)b_k1 * FDIM + colBase + b_n1;

    float acc[2][8][4];
    #pragma unroll
    for (int mt = 0; mt < 2; mt++)
        #pragma unroll
        for (int nt = 0; nt < 8; nt++)
            #pragma unroll
            for (int c = 0; c < 4; c++) acc[mt][nt][c] = 0.f;

    auto load_stage = [&](int s, int k0) {
        uint32_t dA = sA + (uint32_t)(s * 128 * LDA) * 4;
        uint32_t dB = sB + (uint32_t)(s * BK * LDB) * 4;
        CP_ASYNC_CG_Z(dA + (a_row0 * LDA + a_q0) * 4, a_src0 + k0, sz0);
        CP_ASYNC_CG_Z(dA + (a_row1 * LDA + a_q1) * 4, a_src1 + k0, sz1);
        CP_ASYNC_CG(dB + (b_k0 * LDB + b_n0) * 4, b_src0 + (size_t)k0 * FDIM);
        CP_ASYNC_CG(dB + (b_k1 * LDB + b_n1) * 4, b_src1 + (size_t)k0 * FDIM);
    };

    constexpr int NK = K / BK;
    load_stage(0, 0);
    CP_COMMIT();

    #pragma unroll 2
    for (int i = 0; i < NK; i++) {
        if (i + 1 < NK) {
            load_stage((i + 1) & 1, (i + 1) * BK);
            CP_COMMIT();
            CP_WAIT1();
        } else {
            CP_WAIT0();
        }
        __syncthreads();

        const float* as = As[i & 1];
        const float* bs = Bs[i & 1];
        #pragma unroll
        for (int ks = 0; ks < BK / 8; ks++) {
            uint32_t a[2][4], b[8][2];
            #pragma unroll
            for (int mt = 0; mt < 2; mt++) {
                int r = wm * 32 + mt * 16 + gid;
                int c = ks * 8 + tig;
                a[mt][0] = f2tf(as[r * LDA + c]);
                a[mt][1] = f2tf(as[(r + 8) * LDA + c]);
                a[mt][2] = f2tf(as[r * LDA + c + 4]);
                a[mt][3] = f2tf(as[(r + 8) * LDA + c + 4]);
            }
            #pragma unroll
            for (int nt = 0; nt < 8; nt++) {
                int c = wn * 64 + nt * 8 + gid;
                int k1 = ks * 8 + tig;
                b[nt][0] = f2tf(bs[k1 * LDB + c]);
                b[nt][1] = f2tf(bs[(k1 + 4) * LDB + c]);
            }
            #pragma unroll
            for (int mt = 0; mt < 2; mt++)
                #pragma unroll
                for (int nt = 0; nt < 8; nt++) {
                    asm volatile(
                        "mma.sync.aligned.m16n8k8.row.col.f32.tf32.tf32.f32 "
                        "{%0,%1,%2,%3}, {%4,%5,%6,%7}, {%8,%9}, {%0,%1,%2,%3};"
                        : "+f"(acc[mt][nt][0]), "+f"(acc[mt][nt][1]),
                          "+f"(acc[mt][nt][2]), "+f"(acc[mt][nt][3])
                        : "r"(a[mt][0]), "r"(a[mt][1]), "r"(a[mt][2]), "r"(a[mt][3]),
                          "r"(b[nt][0]), "r"(b[nt][1]));
                }
        }
        __syncthreads();
    }

    // ---- epilogue: bias add, store ----
    #pragma unroll
    for (int mt = 0; mt < 2; mt++) {
        int row0 = rowBase + wm * 32 + mt * 16 + gid;
        int row1 = row0 + 8;
        #pragma unroll
        for (int nt = 0; nt < 8; nt++) {
            int col = colBase + wn * 64 + nt * 8 + tig * 2;
            float bx = bias[col], by = bias[col + 1];
            if (row0 < NN) {
                float2 v0 = make_float2(acc[mt][nt][0] + bx, acc[mt][nt][1] + by);
                *reinterpret_cast<float2*>(out + (size_t)row0 * FDIM + col) = v0;
            }
            if (row1 < NN) {
                float2 v1 = make_float2(acc[mt][nt][2] + bx, acc[mt][nt][3] + by);
                *reinterpret_cast<float2*>(out + (size_t)row1 * FDIM + col) = v1;
            }
        }
    }
}

// ---------------- fused edge logits + online segment softmax + aggregation ----------------
__device__ __forceinline__ float lrelu(float v, float s) {
    return v >= 0.f ? v : s * v;
}

__global__ __launch_bounds__(256) void edge_kernel(
    const float* __restrict__ att,   // [16*64]
    const float* __restrict__ bias)  // [64]
{
    int lane = threadIdx.x & 31;
    int warp = threadIdx.x >> 5;
    int n = blockIdx.x * 8 + warp;
    if (n >= NN) return;

    int beg = g_offs[n], end = g_offs[n + 1];

    const float4* xr4  = reinterpret_cast<const float4*>(g_xr) + (size_t)n * 256;
    const float4* att4 = reinterpret_cast<const float4*>(att);

    float4 xrv[8], attv[8];
    #pragma unroll
    for (int k = 0; k < 8; k++) {
        xrv[k]  = xr4[k * 32 + lane];
        attv[k] = att4[k * 32 + lane];
    }

    float m[8], d[8], acc[8][4];
    #pragma unroll
    for (int k = 0; k < 8; k++) {
        m[k] = -1e30f; d[k] = 0.f;
        acc[k][0] = acc[k][1] = acc[k][2] = acc[k][3] = 0.f;
    }

    for (int e = beg; e < end; e++) {
        int s = g_srcs[e];
        const float4* xl4 = reinterpret_cast<const float4*>(g_xl) + (size_t)s * 256;
        float4 xv[8];
        #pragma unroll
        for (int k = 0; k < 8; k++) xv[k] = xl4[k * 32 + lane];

        #pragma unroll
        for (int k = 0; k < 8; k++) {
            float t0 = lrelu(xv[k].x + xrv[k].x, 0.2f);
            float t1 = lrelu(xv[k].y + xrv[k].y, 0.2f);
            float t2 = lrelu(xv[k].z + xrv[k].z, 0.2f);
            float t3 = lrelu(xv[k].w + xrv[k].w, 0.2f);
            float lg = t0 * attv[k].x + t1 * attv[k].y + t2 * attv[k].z + t3 * attv[k].w;
            lg += __shfl_xor_sync(0xffffffffu, lg, 1);
            lg += __shfl_xor_sync(0xffffffffu, lg, 2);
            lg += __shfl_xor_sync(0xffffffffu, lg, 4);
            lg += __shfl_xor_sync(0xffffffffu, lg, 8);
            float nm = fmaxf(m[k], lg);
            float sc = __expf(m[k] - nm);
            float w  = __expf(lg - nm);
            d[k] = d[k] * sc + w;
            m[k] = nm;
            acc[k][0] = acc[k][0] * sc + w * xv[k].x;
            acc[k][1] = acc[k][1] * sc + w * xv[k].y;
            acc[k][2] = acc[k][2] * sc + w * xv[k].z;
            acc[k][3] = acc[k][3] * sc + w * xv[k].w;
        }
    }

    float r0 = 0.f, r1 = 0.f, r2 = 0.f, r3 = 0.f;
    #pragma unroll
    for (int k = 0; k < 8; k++) {
        float inv = 1.f / d[k];
        r0 += acc[k][0] * inv;
        r1 += acc[k][1] * inv;
        r2 += acc[k][2] * inv;
        r3 += acc[k][3] * inv;
    }
    r0 += __shfl_xor_sync(0xffffffffu, r0, 16);
    r1 += __shfl_xor_sync(0xffffffffu, r1, 16);
    r2 += __shfl_xor_sync(0xffffffffu, r2, 16);
    r3 += __shfl_xor_sync(0xffffffffu, r3, 16);

    if (lane < 16) {
        int c = lane * 4;
        const float inv16 = 1.f / 16.f;
        float4 o;
        o.x = lrelu(r0 * inv16 + bias[c + 0], 0.01f);
        o.y = lrelu(r1 * inv16 + bias[c + 1], 0.01f);
        o.z = lrelu(r2 * inv16 + bias[c + 2], 0.01f);
        o.w = lrelu(r3 * inv16 + bias[c + 3], 0.01f);
        *reinterpret_cast<float4*>(g_h + (size_t)n * HID + c) = o;
    }
}

// ---------------- global mean pool + classifier/variance heads ----------------
__global__ void pool_kernel(const int* __restrict__ batch) {
    int t = blockIdx.x * blockDim.x + threadIdx.x;
    if (t >= NN * 16) return;
    int n = t >> 4, q = t & 15;
    int b = batch[n];
    float4 v = *reinterpret_cast<const float4*>(g_h + (size_t)n * HID + q * 4);
    atomicAdd(&g_pool[b * HID + q * 4 + 0], v.x);
    atomicAdd(&g_pool[b * HID + q * 4 + 1], v.y);
    atomicAdd(&g_pool[b * HID + q * 4 + 2], v.z);
    atomicAdd(&g_pool[b * HID + q * 4 + 3], v.w);
    if (q == 0) atomicAdd(&g_pcnt[b], 1);
}

__global__ void head_kernel(const float* __restrict__ Wc, const float* __restrict__ bc,
                            const float* __restrict__ Wv, const float* __restrict__ bv,
                            float* __restrict__ out) {
    __shared__ float p[HID];
    int b = blockIdx.x, c = threadIdx.x;
    float cnt = fmaxf((float)g_pcnt[b], 1.f);
    p[c] = g_pool[b * HID + c] / cnt;
    __syncthreads();
    if (c < 10) {
        float s = bc[c];
        #pragma unroll 8
        for (int k = 0; k < HID; k++) s += p[k] * Wc[k * 10 + c];
        out[b * 10 + c] = s;                 // logits [64,10]
    } else if (c == 10) {
        float s = bv[0];
        #pragma unroll 8
        for (int k = 0; k < HID; k++) s += p[k] * Wv[k];
        out[BB * 10 + b] = s;                // log_var [64,1] after logits
    }
}

// ---------------- launch ----------------
extern "C" void kernel_launch(void* const* d_in, const int* in_sizes, int n_in,
                              void* d_out, int out_size) {
    const float* x     = (const float*)d_in[0];
    const int*   ei    = (const int*)  d_in[1];
    const int*   batch = (const int*)  d_in[2];
    const float* W1l   = (const float*)d_in[3];
    const float* b1l   = (const float*)d_in[4];
    const float* W1r   = (const float*)d_in[5];
    const float* b1r   = (const float*)d_in[6];
    const float* att1  = (const float*)d_in[7];
    const float* bias1 = (const float*)d_in[8];
    const float* W2l   = (const float*)d_in[9];
    const float* b2l   = (const float*)d_in[10];
    const float* W2r   = (const float*)d_in[11];
    const float* b2r   = (const float*)d_in[12];
    const float* att2  = (const float*)d_in[13];
    const float* bias2 = (const float*)d_in[14];
    const float* Wc    = (const float*)d_in[15];
    const float* bc    = (const float*)d_in[16];
    const float* Wv    = (const float*)d_in[17];
    const float* bv    = (const float*)d_in[18];
    float* out = (float*)d_out;

    // CSR by dst (built once, reused by both layers)
    zero_kernel<<<(NN + 255) / 256, 256>>>();
    hist_kernel<<<(ETOT + 255) / 256, 256>>>(ei);
    scan_kernel<<<1, 1024>>>();
    scatter_kernel<<<(ETOT + 255) / 256, 256>>>(ei);

    dim3 ggrid((NN + 127) / 128, FDIM / 128, 2);

    // layer 1
    gemm_tc_kernel<128, false><<<ggrid, 256>>>(x, W1l, b1l, W1r, b1r);
    edge_kernel<<<(NN + 7) / 8, 256>>>(att1, bias1);

    // layer 2 (reads g_h, overwrites g_xl/g_xr, then g_h)
    gemm_tc_kernel<64, true><<<ggrid, 256>>>(nullptr, W2l, b2l, W2r, b2r);
    edge_kernel<<<(NN + 7) / 8, 256>>>(att2, bias2);

    // pooling + heads
    pool_kernel<<<(NN * 16 + 255) / 256, 256>>>(batch);
    head_kernel<<<BB, HID>>>(Wc, bc, Wv, bv, out);
}

// round 7
// speedup vs baseline: 1.5349x; 1.0825x over previous
#include <cuda_runtime.h>
#include <cstdint>
#include <cstddef>

#define NN   20000
#define EE   160000
#define ETOT (EE + NN)
#define BB   64
#define HID  64
#define FDIM 1024  /* HEADS*NHID = 16*64 */

// ---------------- scratch (device globals; no allocation) ----------------
__device__ __align__(16) float g_xl[(size_t)NN * FDIM];   // 81.9 MB
__device__ __align__(16) float g_xr[(size_t)NN * FDIM];   // 81.9 MB
__device__ __align__(16) float g_h [(size_t)NN * HID];    // 5.1 MB
__device__ int   g_cnt [NN];
__device__ int   g_offs[NN + 1];
__device__ int   g_cursor[NN];
__device__ int   g_srcs[ETOT];
__device__ float g_pool[BB * HID];
__device__ int   g_pcnt[BB];

// ---------------- CSR construction ----------------
__global__ void zero_kernel() {
    int i = blockIdx.x * blockDim.x + threadIdx.x;
    if (i < NN) g_cnt[i] = 0;
    if (i < BB * HID) g_pool[i] = 0.f;
    if (i < BB) g_pcnt[i] = 0;
}

__global__ void hist_kernel(const int* __restrict__ ei) {
    int i = blockIdx.x * blockDim.x + threadIdx.x;
    if (i >= ETOT) return;
    int d = (i < EE) ? ei[EE + i] : (i - EE);
    atomicAdd(&g_cnt[d], 1);
}

__global__ void scan_kernel() {
    __shared__ int ps[1024];
    const int CH = 20;
    int tid = threadIdx.x;
    int base = tid * CH;
    int local[CH];
    int s = 0;
    #pragma unroll
    for (int i = 0; i < CH; i++) {
        int idx = base + i;
        int v = (idx < NN) ? g_cnt[idx] : 0;
        local[i] = s;
        s += v;
    }
    ps[tid] = s;
    __syncthreads();
    for (int off = 1; off < 1024; off <<= 1) {
        int v = (tid >= off) ? ps[tid - off] : 0;
        __syncthreads();
        ps[tid] += v;
        __syncthreads();
    }
    int pre = (tid == 0) ? 0 : ps[tid - 1];
    #pragma unroll
    for (int i = 0; i < CH; i++) {
        int idx = base + i;
        if (idx < NN) {
            int o = pre + local[i];
            g_offs[idx] = o;
            g_cursor[idx] = o;
        }
    }
    if (tid == 1023) g_offs[NN] = ps[1023];
}

__global__ void scatter_kernel(const int* __restrict__ ei) {
    int i = blockIdx.x * blockDim.x + threadIdx.x;
    if (i >= ETOT) return;
    int s, d;
    if (i < EE) { s = ei[i]; d = ei[EE + i]; }
    else        { s = d = i - EE; }
    int pos = atomicAdd(&g_cursor[d], 1);
    g_srcs[pos] = s;
}

// ---------------- tf32 tensor-core dual GEMM (4-stage cp.async) --------------
// out{l,r}[NN,1024] = A[NN,K] @ W{l,r}[K,1024] + b{l,r}; blockIdx.z selects l/r.
// 128x128 tile, BK=8, 4-stage pipeline, 1 sync/iter, XOR-swizzled B smem.

#define CP_ASYNC_CG(dst, src) \
    asm volatile("cp.async.cg.shared.global [%0], [%1], 16;" :: "r"(dst), "l"(src))
#define CP_ASYNC_CG_Z(dst, src, sz) \
    asm volatile("cp.async.cg.shared.global [%0], [%1], 16, %2;" :: "r"(dst), "l"(src), "r"(sz))
#define CP_COMMIT() asm volatile("cp.async.commit_group;")
#define CP_WAIT2()  asm volatile("cp.async.wait_group 2;")

__device__ __forceinline__ uint32_t f2tf(float x) {
    uint32_t r;
    asm("cvt.rna.tf32.f32 %0, %1;" : "=r"(r) : "f"(x));
    return r;
}

template <int K, bool A_IS_H>
__global__ __launch_bounds__(256) void gemm_tc_kernel(
    const float* __restrict__ Ain,
    const float* __restrict__ Wl, const float* __restrict__ bl,
    const float* __restrict__ Wr, const float* __restrict__ br)
{
    const float* A    = A_IS_H ? g_h : Ain;
    const float* W    = blockIdx.z ? Wr : Wl;
    const float* bias = blockIdx.z ? br : bl;
    float*       out  = blockIdx.z ? g_xr : g_xl;

    constexpr int BK  = 8;
    constexpr int S   = 4;
    constexpr int LDA = 12;    // As[m][k]: 48B rows, conflict-free frag banks
    constexpr int LDB = 128;   // Bs[k][n]: XOR-swizzled, conflict-free

    __shared__ float As[S][128 * LDA];   // 24 KB
    __shared__ float Bs[S][BK * LDB];    // 16 KB

    int tid  = threadIdx.x;
    int lane = tid & 31, warp = tid >> 5;
    int wm = warp >> 1, wn = warp & 1;
    int gid = lane >> 2, tig = lane & 3;

    int rowBase = blockIdx.x * 128;
    int colBase = blockIdx.y * 128;

    uint32_t sA = (uint32_t)__cvta_generic_to_shared(&As[0][0]);
    uint32_t sB = (uint32_t)__cvta_generic_to_shared(&Bs[0][0]);

    // A load: one float4 per thread per stage
    int a_row = tid >> 1, a_q = (tid & 1) << 2;
    int rg = rowBase + a_row;
    int a_sz = (rg < NN) ? 16 : 0;
    const float* a_src = A + (size_t)(rg < NN ? rg : 0) * K + a_q;
    uint32_t a_dst = (uint32_t)(a_row * LDA + a_q) * 4;
    // B load: one float4 per thread per stage, XOR swizzle j' = j ^ ((k&3)<<1)
    int b_k = tid >> 5, b_j = tid & 31;
    int b_js = b_j ^ ((b_k & 3) << 1);
    const float* b_src = W + (size_t)b_k * FDIM + colBase + (b_j << 2);
    uint32_t b_dst = (uint32_t)(b_k * LDB + (b_js << 2)) * 4;

    float acc[2][8][4];
    #pragma unroll
    for (int mt = 0; mt < 2; mt++)
        #pragma unroll
        for (int nt = 0; nt < 8; nt++)
            #pragma unroll
            for (int c = 0; c < 4; c++) acc[mt][nt][c] = 0.f;

    auto load_stage = [&](int s, int k0) {
        CP_ASYNC_CG_Z(sA + (uint32_t)(s * 128 * LDA) * 4 + a_dst, a_src + k0, a_sz);
        CP_ASYNC_CG(sB + (uint32_t)(s * BK * LDB) * 4 + b_dst, b_src + (size_t)k0 * FDIM);
    };

    constexpr int NK = K / BK;
    #pragma unroll
    for (int s = 0; s < S - 1; s++) {
        load_stage(s, s * BK);
        CP_COMMIT();
    }

    int r0base = wm * 32 + gid;
    int jbase  = wn * 16 + (gid >> 2);   // float4-column base (pre-swizzle)
    int cl     = gid & 3;                // word within float4
    int sw     = tig << 1;               // swizzle XOR term (same for rows tig, tig+4)

    for (int i = 0; i < NK; i++) {
        CP_WAIT2();
        __syncthreads();

        const float* as = As[i & (S - 1)];
        const float* bs = Bs[i & (S - 1)];

        uint32_t a[2][4], b[8][2];
        #pragma unroll
        for (int mt = 0; mt < 2; mt++) {
            int r = r0base + mt * 16;
            a[mt][0] = f2tf(as[r * LDA + tig]);
            a[mt][1] = f2tf(as[(r + 8) * LDA + tig]);
            a[mt][2] = f2tf(as[r * LDA + tig + 4]);
            a[mt][3] = f2tf(as[(r + 8) * LDA + tig + 4]);
        }
        #pragma unroll
        for (int nt = 0; nt < 8; nt++) {
            int j  = jbase + nt * 2;         // float4 column of B element
            int w0 = ((j ^ sw) << 2) + cl;   // XOR applied AFTER nt offset
            b[nt][0] = f2tf(bs[tig * LDB + w0]);
            b[nt][1] = f2tf(bs[(tig + 4) * LDB + w0]);
        }
        #pragma unroll
        for (int mt = 0; mt < 2; mt++)
            #pragma unroll
            for (int nt = 0; nt < 8; nt++) {
                asm volatile(
                    "mma.sync.aligned.m16n8k8.row.col.f32.tf32.tf32.f32 "
                    "{%0,%1,%2,%3}, {%4,%5,%6,%7}, {%8,%9}, {%0,%1,%2,%3};"
                    : "+f"(acc[mt][nt][0]), "+f"(acc[mt][nt][1]),
                      "+f"(acc[mt][nt][2]), "+f"(acc[mt][nt][3])
                    : "r"(a[mt][0]), "r"(a[mt][1]), "r"(a[mt][2]), "r"(a[mt][3]),
                      "r"(b[nt][0]), "r"(b[nt][1]));
            }

        int nx = i + S - 1;
        if (nx < NK) load_stage(nx & (S - 1), nx * BK);
        CP_COMMIT();   // empty group when nx >= NK keeps wait_group math uniform
    }

    // ---- epilogue ----
    #pragma unroll
    for (int mt = 0; mt < 2; mt++) {
        int row0 = rowBase + wm * 32 + mt * 16 + gid;
        int row1 = row0 + 8;
        #pragma unroll
        for (int nt = 0; nt < 8; nt++) {
            int col = colBase + wn * 64 + nt * 8 + tig * 2;
            float bx = bias[col], by = bias[col + 1];
            if (row0 < NN) {
                float2 v0 = make_float2(acc[mt][nt][0] + bx, acc[mt][nt][1] + by);
                *reinterpret_cast<float2*>(out + (size_t)row0 * FDIM + col) = v0;
            }
            if (row1 < NN) {
                float2 v1 = make_float2(acc[mt][nt][2] + bx, acc[mt][nt][3] + by);
                *reinterpret_cast<float2*>(out + (size_t)row1 * FDIM + col) = v1;
            }
        }
    }
}

// ---------------- fused edge logits + segment softmax + aggregation ----------
// One warp per dst node. Logits are tiny, so plain exp without max-subtraction
// is safe and removes the loop-carried max chain. 2 edges/iter for MLP.
// FINAL fuses global mean pooling.
__device__ __forceinline__ float lrelu(float v, float s) {
    return v >= 0.f ? v : s * v;
}

template <bool FINAL>
__global__ __launch_bounds__(256) void edge_kernel(
    const float* __restrict__ att,    // [16*64]
    const float* __restrict__ bias,   // [64]
    const int*   __restrict__ batch)  // [NN] (FINAL only)
{
    __shared__ float4 att_s[256];
    if (threadIdx.x < 256)
        att_s[threadIdx.x] = reinterpret_cast<const float4*>(att)[threadIdx.x];
    __syncthreads();

    int lane = threadIdx.x & 31;
    int warp = threadIdx.x >> 5;
    int n = blockIdx.x * 8 + warp;
    if (n >= NN) return;

    int beg = g_offs[n], end = g_offs[n + 1];

    const float4* xr4 = reinterpret_cast<const float4*>(g_xr) + (size_t)n * 256;

    float4 xrv[8];
    #pragma unroll
    for (int k = 0; k < 8; k++) xrv[k] = xr4[k * 32 + lane];

    float d[8], acc[8][4];
    #pragma unroll
    for (int k = 0; k < 8; k++) {
        d[k] = 0.f;
        acc[k][0] = acc[k][1] = acc[k][2] = acc[k][3] = 0.f;
    }

    int e = beg;
    for (; e + 1 < end; e += 2) {
        int s0 = g_srcs[e], s1 = g_srcs[e + 1];
        const float4* x0 = reinterpret_cast<const float4*>(g_xl) + (size_t)s0 * 256;
        const float4* x1 = reinterpret_cast<const float4*>(g_xl) + (size_t)s1 * 256;
        float4 xv0[8], xv1[8];
        #pragma unroll
        for (int k = 0; k < 8; k++) xv0[k] = x0[k * 32 + lane];
        #pragma unroll
        for (int k = 0; k < 8; k++) xv1[k] = x1[k * 32 + lane];

        #pragma unroll
        for (int k = 0; k < 8; k++) {
            float4 av = att_s[k * 32 + lane];
            float l0 = lrelu(xv0[k].x + xrv[k].x, 0.2f) * av.x
                     + lrelu(xv0[k].y + xrv[k].y, 0.2f) * av.y
                     + lrelu(xv0[k].z + xrv[k].z, 0.2f) * av.z
                     + lrelu(xv0[k].w + xrv[k].w, 0.2f) * av.w;
            float l1 = lrelu(xv1[k].x + xrv[k].x, 0.2f) * av.x
                     + lrelu(xv1[k].y + xrv[k].y, 0.2f) * av.y
                     + lrelu(xv1[k].z + xrv[k].z, 0.2f) * av.z
                     + lrelu(xv1[k].w + xrv[k].w, 0.2f) * av.w;
            #pragma unroll
            for (int o = 1; o <= 8; o <<= 1) {
                l0 += __shfl_xor_sync(0xffffffffu, l0, o);
                l1 += __shfl_xor_sync(0xffffffffu, l1, o);
            }
            float w0 = __expf(l0), w1 = __expf(l1);
            d[k] += w0 + w1;
            acc[k][0] += w0 * xv0[k].x + w1 * xv1[k].x;
            acc[k][1] += w0 * xv0[k].y + w1 * xv1[k].y;
            acc[k][2] += w0 * xv0[k].z + w1 * xv1[k].z;
            acc[k][3] += w0 * xv0[k].w + w1 * xv1[k].w;
        }
    }
    if (e < end) {
        int s0 = g_srcs[e];
        const float4* x0 = reinterpret_cast<const float4*>(g_xl) + (size_t)s0 * 256;
        float4 xv0[8];
        #pragma unroll
        for (int k = 0; k < 8; k++) xv0[k] = x0[k * 32 + lane];
        #pragma unroll
        for (int k = 0; k < 8; k++) {
            float4 av = att_s[k * 32 + lane];
            float l0 = lrelu(xv0[k].x + xrv[k].x, 0.2f) * av.x
                     + lrelu(xv0[k].y + xrv[k].y, 0.2f) * av.y
                     + lrelu(xv0[k].z + xrv[k].z, 0.2f) * av.z
                     + lrelu(xv0[k].w + xrv[k].w, 0.2f) * av.w;
            #pragma unroll
            for (int o = 1; o <= 8; o <<= 1)
                l0 += __shfl_xor_sync(0xffffffffu, l0, o);
            float w0 = __expf(l0);
            d[k] += w0;
            acc[k][0] += w0 * xv0[k].x;
            acc[k][1] += w0 * xv0[k].y;
            acc[k][2] += w0 * xv0[k].z;
            acc[k][3] += w0 * xv0[k].w;
        }
    }

    float r0 = 0.f, r1 = 0.f, r2 = 0.f, r3 = 0.f;
    #pragma unroll
    for (int k = 0; k < 8; k++) {
        float inv = 1.f / d[k];
        r0 += acc[k][0] * inv;
        r1 += acc[k][1] * inv;
        r2 += acc[k][2] * inv;
        r3 += acc[k][3] * inv;
    }
    r0 += __shfl_xor_sync(0xffffffffu, r0, 16);
    r1 += __shfl_xor_sync(0xffffffffu, r1, 16);
    r2 += __shfl_xor_sync(0xffffffffu, r2, 16);
    r3 += __shfl_xor_sync(0xffffffffu, r3, 16);

    if (lane < 16) {
        int c = lane * 4;
        const float inv16 = 1.f / 16.f;
        float o0 = lrelu(r0 * inv16 + bias[c + 0], 0.01f);
        float o1 = lrelu(r1 * inv16 + bias[c + 1], 0.01f);
        float o2 = lrelu(r2 * inv16 + bias[c + 2], 0.01f);
        float o3 = lrelu(r3 * inv16 + bias[c + 3], 0.01f);
        if (FINAL) {
            int b = batch[n];
            atomicAdd(&g_pool[b * HID + c + 0], o0);
            atomicAdd(&g_pool[b * HID + c + 1], o1);
            atomicAdd(&g_pool[b * HID + c + 2], o2);
            atomicAdd(&g_pool[b * HID + c + 3], o3);
            if (lane == 0) atomicAdd(&g_pcnt[b], 1);
        } else {
            float4 o = make_float4(o0, o1, o2, o3);
            *reinterpret_cast<float4*>(g_h + (size_t)n * HID + c) = o;
        }
    }
}

// ---------------- classifier/variance heads ----------------
__global__ void head_kernel(const float* __restrict__ Wc, const float* __restrict__ bc,
                            const float* __restrict__ Wv, const float* __restrict__ bv,
                            float* __restrict__ out) {
    __shared__ float p[HID];
    int b = blockIdx.x, c = threadIdx.x;
    float cnt = fmaxf((float)g_pcnt[b], 1.f);
    p[c] = g_pool[b * HID + c] / cnt;
    __syncthreads();
    if (c < 10) {
        float s = bc[c];
        #pragma unroll 8
        for (int k = 0; k < HID; k++) s += p[k] * Wc[k * 10 + c];
        out[b * 10 + c] = s;                 // logits [64,10]
    } else if (c == 10) {
        float s = bv[0];
        #pragma unroll 8
        for (int k = 0; k < HID; k++) s += p[k] * Wv[k];
        out[BB * 10 + b] = s;                // log_var [64,1]
    }
}

// ---------------- launch ----------------
extern "C" void kernel_launch(void* const* d_in, const int* in_sizes, int n_in,
                              void* d_out, int out_size) {
    const float* x     = (const float*)d_in[0];
    const int*   ei    = (const int*)  d_in[1];
    const int*   batch = (const int*)  d_in[2];
    const float* W1l   = (const float*)d_in[3];
    const float* b1l   = (const float*)d_in[4];
    const float* W1r   = (const float*)d_in[5];
    const float* b1r   = (const float*)d_in[6];
    const float* att1  = (const float*)d_in[7];
    const float* bias1 = (const float*)d_in[8];
    const float* W2l   = (const float*)d_in[9];
    const float* b2l   = (const float*)d_in[10];
    const float* W2r   = (const float*)d_in[11];
    const float* b2r   = (const float*)d_in[12];
    const float* att2  = (const float*)d_in[13];
    const float* bias2 = (const float*)d_in[14];
    const float* Wc    = (const float*)d_in[15];
    const float* bc    = (const float*)d_in[16];
    const float* Wv    = (const float*)d_in[17];
    const float* bv    = (const float*)d_in[18];
    float* out = (float*)d_out;

    zero_kernel<<<(NN + 255) / 256, 256>>>();
    hist_kernel<<<(ETOT + 255) / 256, 256>>>(ei);
    scan_kernel<<<1, 1024>>>();
    scatter_kernel<<<(ETOT + 255) / 256, 256>>>(ei);

    dim3 ggrid((NN + 127) / 128, FDIM / 128, 2);

    gemm_tc_kernel<128, false><<<ggrid, 256>>>(x, W1l, b1l, W1r, b1r);
    edge_kernel<false><<<(NN + 7) / 8, 256>>>(att1, bias1, batch);

    gemm_tc_kernel<64, true><<<ggrid, 256>>>(nullptr, W2l, b2l, W2r, b2r);
    edge_kernel<true><<<(NN + 7) / 8, 256>>>(att2, bias2, batch);

    head_kernel<<<BB, HID>>>(Wc, bc, Wv, bv, out);
}

// round 8
// speedup vs baseline: 1.7138x; 1.1166x over previous
#include <cuda_runtime.h>
#include <cuda_bf16.h>
#include <cstdint>
#include <cstddef>

#define NN   20000
#define EE   160000
#define ETOT (EE + NN)
#define BB   64
#define HID  64
#define FDIM 1024  /* HEADS*NHID = 16*64 */

// ---------------- scratch (device globals; no allocation) ----------------
__device__ __align__(16) __nv_bfloat16 g_xl[(size_t)NN * FDIM];  // 41 MB
__device__ __align__(16) __nv_bfloat16 g_xr[(size_t)NN * FDIM];  // 41 MB
__device__ __align__(16) float g_h [(size_t)NN * HID];           // 5.1 MB
__device__ int   g_cnt [NN];
__device__ int   g_offs[NN + 1];
__device__ int   g_cursor[NN];
__device__ int   g_srcs[ETOT];
__device__ float g_pool[BB * HID];
__device__ int   g_pcnt[BB];

// ---------------- CSR construction ----------------
__global__ void zero_kernel() {
    int i = blockIdx.x * blockDim.x + threadIdx.x;
    if (i < NN) g_cnt[i] = 0;
    if (i < BB * HID) g_pool[i] = 0.f;
    if (i < BB) g_pcnt[i] = 0;
}

__global__ void hist_kernel(const int* __restrict__ ei) {
    int i = blockIdx.x * blockDim.x + threadIdx.x;
    if (i >= ETOT) return;
    int d = (i < EE) ? ei[EE + i] : (i - EE);
    atomicAdd(&g_cnt[d], 1);
}

__global__ void scan_kernel() {
    __shared__ int ps[1024];
    const int CH = 20;
    int tid = threadIdx.x;
    int base = tid * CH;
    int local[CH];
    int s = 0;
    #pragma unroll
    for (int i = 0; i < CH; i++) {
        int idx = base + i;
        int v = (idx < NN) ? g_cnt[idx] : 0;
        local[i] = s;
        s += v;
    }
    ps[tid] = s;
    __syncthreads();
    for (int off = 1; off < 1024; off <<= 1) {
        int v = (tid >= off) ? ps[tid - off] : 0;
        __syncthreads();
        ps[tid] += v;
        __syncthreads();
    }
    int pre = (tid == 0) ? 0 : ps[tid - 1];
    #pragma unroll
    for (int i = 0; i < CH; i++) {
        int idx = base + i;
        if (idx < NN) {
            int o = pre + local[i];
            g_offs[idx] = o;
            g_cursor[idx] = o;
        }
    }
    if (tid == 1023) g_offs[NN] = ps[1023];
}

__global__ void scatter_kernel(const int* __restrict__ ei) {
    int i = blockIdx.x * blockDim.x + threadIdx.x;
    if (i >= ETOT) return;
    int s, d;
    if (i < EE) { s = ei[i]; d = ei[EE + i]; }
    else        { s = d = i - EE; }
    int pos = atomicAdd(&g_cursor[d], 1);
    g_srcs[pos] = s;
}

// ---------------- tf32 tensor-core dual GEMM (4-stage cp.async) --------------
// out{l,r}[NN,1024] = bf16( A[NN,K] @ W{l,r}[K,1024] + b{l,r} ); z selects l/r.

#define CP_ASYNC_CG(dst, src) \
    asm volatile("cp.async.cg.shared.global [%0], [%1], 16;" :: "r"(dst), "l"(src))
#define CP_ASYNC_CG_Z(dst, src, sz) \
    asm volatile("cp.async.cg.shared.global [%0], [%1], 16, %2;" :: "r"(dst), "l"(src), "r"(sz))
#define CP_COMMIT() asm volatile("cp.async.commit_group;")
#define CP_WAIT2()  asm volatile("cp.async.wait_group 2;")

__device__ __forceinline__ uint32_t f2tf(float x) {
    uint32_t r;
    asm("cvt.rna.tf32.f32 %0, %1;" : "=r"(r) : "f"(x));
    return r;
}

template <int K, bool A_IS_H>
__global__ __launch_bounds__(256) void gemm_tc_kernel(
    const float* __restrict__ Ain,
    const float* __restrict__ Wl, const float* __restrict__ bl,
    const float* __restrict__ Wr, const float* __restrict__ br)
{
    const float* A    = A_IS_H ? g_h : Ain;
    const float* W    = blockIdx.z ? Wr : Wl;
    const float* bias = blockIdx.z ? br : bl;
    __nv_bfloat16* out = blockIdx.z ? g_xr : g_xl;

    constexpr int BK  = 8;
    constexpr int S   = 4;
    constexpr int LDA = 12;
    constexpr int LDB = 128;

    __shared__ float As[S][128 * LDA];   // 24 KB
    __shared__ float Bs[S][BK * LDB];    // 16 KB

    int tid  = threadIdx.x;
    int lane = tid & 31, warp = tid >> 5;
    int wm = warp >> 1, wn = warp & 1;
    int gid = lane >> 2, tig = lane & 3;

    int rowBase = blockIdx.x * 128;
    int colBase = blockIdx.y * 128;

    uint32_t sA = (uint32_t)__cvta_generic_to_shared(&As[0][0]);
    uint32_t sB = (uint32_t)__cvta_generic_to_shared(&Bs[0][0]);

    int a_row = tid >> 1, a_q = (tid & 1) << 2;
    int rg = rowBase + a_row;
    int a_sz = (rg < NN) ? 16 : 0;
    const float* a_src = A + (size_t)(rg < NN ? rg : 0) * K + a_q;
    uint32_t a_dst = (uint32_t)(a_row * LDA + a_q) * 4;
    int b_k = tid >> 5, b_j = tid & 31;
    int b_js = b_j ^ ((b_k & 3) << 1);
    const float* b_src = W + (size_t)b_k * FDIM + colBase + (b_j << 2);
    uint32_t b_dst = (uint32_t)(b_k * LDB + (b_js << 2)) * 4;

    float acc[2][8][4];
    #pragma unroll
    for (int mt = 0; mt < 2; mt++)
        #pragma unroll
        for (int nt = 0; nt < 8; nt++)
            #pragma unroll
            for (int c = 0; c < 4; c++) acc[mt][nt][c] = 0.f;

    auto load_stage = [&](int s, int k0) {
        CP_ASYNC_CG_Z(sA + (uint32_t)(s * 128 * LDA) * 4 + a_dst, a_src + k0, a_sz);
        CP_ASYNC_CG(sB + (uint32_t)(s * BK * LDB) * 4 + b_dst, b_src + (size_t)k0 * FDIM);
    };

    constexpr int NK = K / BK;
    #pragma unroll
    for (int s = 0; s < S - 1; s++) {
        load_stage(s, s * BK);
        CP_COMMIT();
    }

    int r0base = wm * 32 + gid;
    int jbase  = wn * 16 + (gid >> 2);
    int cl     = gid & 3;
    int sw     = tig << 1;

    for (int i = 0; i < NK; i++) {
        CP_WAIT2();
        __syncthreads();

        const float* as = As[i & (S - 1)];
        const float* bs = Bs[i & (S - 1)];

        uint32_t a[2][4], b[8][2];
        #pragma unroll
        for (int mt = 0; mt < 2; mt++) {
            int r = r0base + mt * 16;
            a[mt][0] = f2tf(as[r * LDA + tig]);
            a[mt][1] = f2tf(as[(r + 8) * LDA + tig]);
            a[mt][2] = f2tf(as[r * LDA + tig + 4]);
            a[mt][3] = f2tf(as[(r + 8) * LDA + tig + 4]);
        }
        #pragma unroll
        for (int nt = 0; nt < 8; nt++) {
            int j  = jbase + nt * 2;
            int w0 = ((j ^ sw) << 2) + cl;
            b[nt][0] = f2tf(bs[tig * LDB + w0]);
            b[nt][1] = f2tf(bs[(tig + 4) * LDB + w0]);
        }
        #pragma unroll
        for (int mt = 0; mt < 2; mt++)
            #pragma unroll
            for (int nt = 0; nt < 8; nt++) {
                asm volatile(
                    "mma.sync.aligned.m16n8k8.row.col.f32.tf32.tf32.f32 "
                    "{%0,%1,%2,%3}, {%4,%5,%6,%7}, {%8,%9}, {%0,%1,%2,%3};"
                    : "+f"(acc[mt][nt][0]), "+f"(acc[mt][nt][1]),
                      "+f"(acc[mt][nt][2]), "+f"(acc[mt][nt][3])
                    : "r"(a[mt][0]), "r"(a[mt][1]), "r"(a[mt][2]), "r"(a[mt][3]),
                      "r"(b[nt][0]), "r"(b[nt][1]));
            }

        int nx = i + S - 1;
        if (nx < NK) load_stage(nx & (S - 1), nx * BK);
        CP_COMMIT();
    }

    // ---- epilogue: bias add, bf16 pack, store ----
    #pragma unroll
    for (int mt = 0; mt < 2; mt++) {
        int row0 = rowBase + wm * 32 + mt * 16 + gid;
        int row1 = row0 + 8;
        #pragma unroll
        for (int nt = 0; nt < 8; nt++) {
            int col = colBase + wn * 64 + nt * 8 + tig * 2;
            float bx = bias[col], by = bias[col + 1];
            if (row0 < NN) {
                __nv_bfloat162 v0 = __floats2bfloat162_rn(acc[mt][nt][0] + bx,
                                                          acc[mt][nt][1] + by);
                *reinterpret_cast<__nv_bfloat162*>(out + (size_t)row0 * FDIM + col) = v0;
            }
            if (row1 < NN) {
                __nv_bfloat162 v1 = __floats2bfloat162_rn(acc[mt][nt][2] + bx,
                                                          acc[mt][nt][3] + by);
                *reinterpret_cast<__nv_bfloat162*>(out + (size_t)row1 * FDIM + col) = v1;
            }
        }
    }
}

// ---------------- fused edge logits + segment softmax + aggregation ----------
// One warp per dst node; xl/xr are bf16 (16B chunk = 8 channels per lane).
// Lane l, iter k: head = k*4 + (l>>3), channels (l&7)*8 .. +8.
// Logit reduce: shfl_xor 1,2,4 (8-lane head group); head-mean: shfl_xor 8,16.
__device__ __forceinline__ float lrelu(float v, float s) {
    return v >= 0.f ? v : s * v;
}

__device__ __forceinline__ void bf8_to_f32(const uint4& u, float* f) {
    float2 p;
    p = __bfloat1622float2(*reinterpret_cast<const __nv_bfloat162*>(&u.x));
    f[0] = p.x; f[1] = p.y;
    p = __bfloat1622float2(*reinterpret_cast<const __nv_bfloat162*>(&u.y));
    f[2] = p.x; f[3] = p.y;
    p = __bfloat1622float2(*reinterpret_cast<const __nv_bfloat162*>(&u.z));
    f[4] = p.x; f[5] = p.y;
    p = __bfloat1622float2(*reinterpret_cast<const __nv_bfloat162*>(&u.w));
    f[6] = p.x; f[7] = p.y;
}

template <bool FINAL>
__global__ __launch_bounds__(256, 2) void edge_kernel(
    const float* __restrict__ att,    // [16*64]
    const float* __restrict__ bias,   // [64]
    const int*   __restrict__ batch)  // [NN] (FINAL only)
{
    __shared__ float att_s[FDIM];
    reinterpret_cast<float4*>(att_s)[threadIdx.x] =
        reinterpret_cast<const float4*>(att)[threadIdx.x];
    __syncthreads();

    int lane = threadIdx.x & 31;
    int warp = threadIdx.x >> 5;
    int n = blockIdx.x * 8 + warp;
    if (n >= NN) return;

    int beg = g_offs[n], end = g_offs[n + 1];
    int grp = lane >> 3, sub = lane & 7;

    const uint4* xlp = reinterpret_cast<const uint4*>(g_xl);
    const uint4* xrp = reinterpret_cast<const uint4*>(g_xr) + (size_t)n * 128;

    uint4 xr_raw[4];
    #pragma unroll
    for (int k = 0; k < 4; k++) xr_raw[k] = xrp[k * 32 + lane];

    float d[4], acc[4][8];
    #pragma unroll
    for (int k = 0; k < 4; k++) {
        d[k] = 0.f;
        #pragma unroll
        for (int j = 0; j < 8; j++) acc[k][j] = 0.f;
    }

    int e = beg;
    for (; e + 1 < end; e += 2) {
        int s0 = g_srcs[e], s1 = g_srcs[e + 1];
        const uint4* x0p = xlp + (size_t)s0 * 128;
        const uint4* x1p = xlp + (size_t)s1 * 128;
        uint4 xv0[4], xv1[4];
        #pragma unroll
        for (int k = 0; k < 4; k++) xv0[k] = x0p[k * 32 + lane];
        #pragma unroll
        for (int k = 0; k < 4; k++) xv1[k] = x1p[k * 32 + lane];

        #pragma unroll
        for (int k = 0; k < 4; k++) {
            float xr8[8], x0[8], x1[8];
            bf8_to_f32(xr_raw[k], xr8);
            bf8_to_f32(xv0[k], x0);
            bf8_to_f32(xv1[k], x1);
            const float* av = att_s + ((k * 4 + grp) * 64 + sub * 8);
            float l0 = 0.f, l1 = 0.f;
            #pragma unroll
            for (int j = 0; j < 8; j++) {
                float a = av[j];
                l0 += lrelu(x0[j] + xr8[j], 0.2f) * a;
                l1 += lrelu(x1[j] + xr8[j], 0.2f) * a;
            }
            #pragma unroll
            for (int o = 1; o <= 4; o <<= 1) {
                l0 += __shfl_xor_sync(0xffffffffu, l0, o);
                l1 += __shfl_xor_sync(0xffffffffu, l1, o);
            }
            float w0 = __expf(l0), w1 = __expf(l1);
            d[k] += w0 + w1;
            #pragma unroll
            for (int j = 0; j < 8; j++)
                acc[k][j] += w0 * x0[j] + w1 * x1[j];
        }
    }
    if (e < end) {
        int s0 = g_srcs[e];
        const uint4* x0p = xlp + (size_t)s0 * 128;
        uint4 xv0[4];
        #pragma unroll
        for (int k = 0; k < 4; k++) xv0[k] = x0p[k * 32 + lane];
        #pragma unroll
        for (int k = 0; k < 4; k++) {
            float xr8[8], x0[8];
            bf8_to_f32(xr_raw[k], xr8);
            bf8_to_f32(xv0[k], x0);
            const float* av = att_s + ((k * 4 + grp) * 64 + sub * 8);
            float l0 = 0.f;
            #pragma unroll
            for (int j = 0; j < 8; j++)
                l0 += lrelu(x0[j] + xr8[j], 0.2f) * av[j];
            #pragma unroll
            for (int o = 1; o <= 4; o <<= 1)
                l0 += __shfl_xor_sync(0xffffffffu, l0, o);
            float w0 = __expf(l0);
            d[k] += w0;
            #pragma unroll
            for (int j = 0; j < 8; j++)
                acc[k][j] += w0 * x0[j];
        }
    }

    // normalize per head, sum the 4 local heads, then reduce across groups
    float r[8];
    #pragma unroll
    for (int j = 0; j < 8; j++) r[j] = 0.f;
    #pragma unroll
    for (int k = 0; k < 4; k++) {
        float inv = 1.f / d[k];
        #pragma unroll
        for (int j = 0; j < 8; j++) r[j] += acc[k][j] * inv;
    }
    #pragma unroll
    for (int j = 0; j < 8; j++) {
        r[j] += __shfl_xor_sync(0xffffffffu, r[j], 8);
        r[j] += __shfl_xor_sync(0xffffffffu, r[j], 16);
    }

    if (lane < 8) {
        int c = lane * 8;
        const float inv16 = 1.f / 16.f;
        float o[8];
        #pragma unroll
        for (int j = 0; j < 8; j++)
            o[j] = lrelu(r[j] * inv16 + bias[c + j], 0.01f);
        if (FINAL) {
            int b = batch[n];
            #pragma unroll
            for (int j = 0; j < 8; j++)
                atomicAdd(&g_pool[b * HID + c + j], o[j]);
            if (lane == 0) atomicAdd(&g_pcnt[b], 1);
        } else {
            float4 v0 = make_float4(o[0], o[1], o[2], o[3]);
            float4 v1 = make_float4(o[4], o[5], o[6], o[7]);
            *reinterpret_cast<float4*>(g_h + (size_t)n * HID + c)     = v0;
            *reinterpret_cast<float4*>(g_h + (size_t)n * HID + c + 4) = v1;
        }
    }
}

// ---------------- classifier/variance heads ----------------
__global__ void head_kernel(const float* __restrict__ Wc, const float* __restrict__ bc,
                            const float* __restrict__ Wv, const float* __restrict__ bv,
                            float* __restrict__ out) {
    __shared__ float p[HID];
    int b = blockIdx.x, c = threadIdx.x;
    float cnt = fmaxf((float)g_pcnt[b], 1.f);
    p[c] = g_pool[b * HID + c] / cnt;
    __syncthreads();
    if (c < 10) {
        float s = bc[c];
        #pragma unroll 8
        for (int k = 0; k < HID; k++) s += p[k] * Wc[k * 10 + c];
        out[b * 10 + c] = s;                 // logits [64,10]
    } else if (c == 10) {
        float s = bv[0];
        #pragma unroll 8
        for (int k = 0; k < HID; k++) s += p[k] * Wv[k];
        out[BB * 10 + b] = s;                // log_var [64,1]
    }
}

// ---------------- launch ----------------
extern "C" void kernel_launch(void* const* d_in, const int* in_sizes, int n_in,
                              void* d_out, int out_size) {
    const float* x     = (const float*)d_in[0];
    const int*   ei    = (const int*)  d_in[1];
    const int*   batch = (const int*)  d_in[2];
    const float* W1l   = (const float*)d_in[3];
    const float* b1l   = (const float*)d_in[4];
    const float* W1r   = (const float*)d_in[5];
    const float* b1r   = (const float*)d_in[6];
    const float* att1  = (const float*)d_in[7];
    const float* bias1 = (const float*)d_in[8];
    const float* W2l   = (const float*)d_in[9];
    const float* b2l   = (const float*)d_in[10];
    const float* W2r   = (const float*)d_in[11];
    const float* b2r   = (const float*)d_in[12];
    const float* att2  = (const float*)d_in[13];
    const float* bias2 = (const float*)d_in[14];
    const float* Wc    = (const float*)d_in[15];
    const float* bc    = (const float*)d_in[16];
    const float* Wv    = (const float*)d_in[17];
    const float* bv    = (const float*)d_in[18];
    float* out = (float*)d_out;

    zero_kernel<<<(NN + 255) / 256, 256>>>();
    hist_kernel<<<(ETOT + 255) / 256, 256>>>(ei);
    scan_kernel<<<1, 1024>>>();
    scatter_kernel<<<(ETOT + 255) / 256, 256>>>(ei);

    dim3 ggrid((NN + 127) / 128, FDIM / 128, 2);

    gemm_tc_kernel<128, false><<<ggrid, 256>>>(x, W1l, b1l, W1r, b1r);
    edge_kernel<false><<<(NN + 7) / 8, 256>>>(att1, bias1, batch);

    gemm_tc_kernel<64, true><<<ggrid, 256>>>(nullptr, W2l, b2l, W2r, b2r);
    edge_kernel<true><<<(NN + 7) / 8, 256>>>(att2, bias2, batch);

    head_kernel<<<BB, HID>>>(Wc, bc, Wv, bv, out);
}

// round 9
// speedup vs baseline: 1.8027x; 1.0519x over previous
#include <cuda_runtime.h>
#include <cuda_bf16.h>
#include <cstdint>
#include <cstddef>

#define NN   20000
#define EE   160000
#define ETOT (EE + NN)
#define BB   64
#define HID  64
#define FDIM 1024  /* HEADS*NHID = 16*64 */

// ---------------- scratch (device globals; no allocation) ----------------
__device__ __align__(16) __nv_bfloat16 g_xl[(size_t)NN * FDIM];  // 41 MB
__device__ __align__(16) __nv_bfloat16 g_xr[(size_t)NN * FDIM];  // 41 MB
__device__ __align__(16) float g_h  [(size_t)NN * HID];          // 5.1 MB (tf32-rounded)
__device__ __align__(16) float g_xa [(size_t)NN * 128];          // 10.2 MB x, tf32-rounded
__device__ __align__(16) float g_w1l[128 * FDIM];
__device__ __align__(16) float g_w1r[128 * FDIM];
__device__ __align__(16) float g_w2l[64 * FDIM];
__device__ __align__(16) float g_w2r[64 * FDIM];
__device__ int   g_cnt [NN];
__device__ int   g_offs[NN + 1];
__device__ int   g_cursor[NN];
__device__ int   g_srcs[ETOT];
__device__ float g_pool[BB * HID];
__device__ int   g_pcnt[BB];

__device__ __forceinline__ uint32_t f2tf(float x) {
    uint32_t r;
    asm("cvt.rna.tf32.f32 %0, %1;" : "=r"(r) : "f"(x));
    return r;
}
__device__ __forceinline__ float4 round4(float4 v) {
    v.x = __uint_as_float(f2tf(v.x));
    v.y = __uint_as_float(f2tf(v.y));
    v.z = __uint_as_float(f2tf(v.z));
    v.w = __uint_as_float(f2tf(v.w));
    return v;
}

// ---------------- pre-rounding kernels (run once per launch; tiny) -----------
__global__ void round_x_kernel(const float* __restrict__ x) {
    int i = blockIdx.x * blockDim.x + threadIdx.x;
    if (i < NN * 128 / 4)
        reinterpret_cast<float4*>(g_xa)[i] =
            round4(reinterpret_cast<const float4*>(x)[i]);
}

template <int LAYER>
__global__ void round_w_kernel(const float* __restrict__ wl,
                               const float* __restrict__ wr) {
    constexpr int NW = (LAYER == 1 ? 128 : 64) * FDIM / 4;
    float* dl = (LAYER == 1) ? g_w1l : g_w2l;
    float* dr = (LAYER == 1) ? g_w1r : g_w2r;
    int i = blockIdx.x * blockDim.x + threadIdx.x;
    if (i < NW) {
        reinterpret_cast<float4*>(dl)[i] = round4(reinterpret_cast<const float4*>(wl)[i]);
        reinterpret_cast<float4*>(dr)[i] = round4(reinterpret_cast<const float4*>(wr)[i]);
    }
}

// ---------------- CSR construction ----------------
__global__ void zero_kernel() {
    int i = blockIdx.x * blockDim.x + threadIdx.x;
    if (i < NN) g_cnt[i] = 0;
    if (i < BB * HID) g_pool[i] = 0.f;
    if (i < BB) g_pcnt[i] = 0;
}

__global__ void hist_kernel(const int* __restrict__ ei) {
    int i = blockIdx.x * blockDim.x + threadIdx.x;
    if (i >= ETOT) return;
    int d = (i < EE) ? ei[EE + i] : (i - EE);
    atomicAdd(&g_cnt[d], 1);
}

__global__ void scan_kernel() {
    __shared__ int ps[1024];
    const int CH = 20;
    int tid = threadIdx.x;
    int base = tid * CH;
    int local[CH];
    int s = 0;
    #pragma unroll
    for (int i = 0; i < CH; i++) {
        int idx = base + i;
        int v = (idx < NN) ? g_cnt[idx] : 0;
        local[i] = s;
        s += v;
    }
    ps[tid] = s;
    __syncthreads();
    for (int off = 1; off < 1024; off <<= 1) {
        int v = (tid >= off) ? ps[tid - off] : 0;
        __syncthreads();
        ps[tid] += v;
        __syncthreads();
    }
    int pre = (tid == 0) ? 0 : ps[tid - 1];
    #pragma unroll
    for (int i = 0; i < CH; i++) {
        int idx = base + i;
        if (idx < NN) {
            int o = pre + local[i];
            g_offs[idx] = o;
            g_cursor[idx] = o;
        }
    }
    if (tid == 1023) g_offs[NN] = ps[1023];
}

__global__ void scatter_kernel(const int* __restrict__ ei) {
    int i = blockIdx.x * blockDim.x + threadIdx.x;
    if (i >= ETOT) return;
    int s, d;
    if (i < EE) { s = ei[i]; d = ei[EE + i]; }
    else        { s = d = i - EE; }
    int pos = atomicAdd(&g_cursor[d], 1);
    g_srcs[pos] = s;
}

// ---------------- tf32 tensor-core dual GEMM (4-stage cp.async) --------------
// Operands are PRE-ROUNDED to tf32 (RNA); hot loop feeds raw bits to the mma —
// no CVTs in the loop. out = bf16(A @ W + b). blockIdx.z selects l/r.

#define CP_ASYNC_CG(dst, src) \
    asm volatile("cp.async.cg.shared.global [%0], [%1], 16;" :: "r"(dst), "l"(src))
#define CP_ASYNC_CG_Z(dst, src, sz) \
    asm volatile("cp.async.cg.shared.global [%0], [%1], 16, %2;" :: "r"(dst), "l"(src), "r"(sz))
#define CP_COMMIT() asm volatile("cp.async.commit_group;")
#define CP_WAIT2()  asm volatile("cp.async.wait_group 2;")

template <int K, int LAYER>
__global__ __launch_bounds__(256) void gemm_tc_kernel(
    const float* __restrict__ bl, const float* __restrict__ br)
{
    const float* A    = (LAYER == 1) ? g_xa : g_h;
    const float* W    = (LAYER == 1) ? (blockIdx.z ? g_w1r : g_w1l)
                                     : (blockIdx.z ? g_w2r : g_w2l);
    const float* bias = blockIdx.z ? br : bl;
    __nv_bfloat16* out = blockIdx.z ? g_xr : g_xl;

    constexpr int BK  = 8;
    constexpr int S   = 4;
    constexpr int LDA = 12;
    constexpr int LDB = 128;

    __shared__ float As[S][128 * LDA];   // 24 KB
    __shared__ float Bs[S][BK * LDB];    // 16 KB

    int tid  = threadIdx.x;
    int lane = tid & 31, warp = tid >> 5;
    int wm = warp >> 1, wn = warp & 1;
    int gid = lane >> 2, tig = lane & 3;

    int rowBase = blockIdx.x * 128;
    int colBase = blockIdx.y * 128;

    uint32_t sA = (uint32_t)__cvta_generic_to_shared(&As[0][0]);
    uint32_t sB = (uint32_t)__cvta_generic_to_shared(&Bs[0][0]);

    int a_row = tid >> 1, a_q = (tid & 1) << 2;
    int rg = rowBase + a_row;
    int a_sz = (rg < NN) ? 16 : 0;
    const float* a_src = A + (size_t)(rg < NN ? rg : 0) * K + a_q;
    uint32_t a_dst = (uint32_t)(a_row * LDA + a_q) * 4;
    int b_k = tid >> 5, b_j = tid & 31;
    int b_js = b_j ^ ((b_k & 3) << 1);
    const float* b_src = W + (size_t)b_k * FDIM + colBase + (b_j << 2);
    uint32_t b_dst = (uint32_t)(b_k * LDB + (b_js << 2)) * 4;

    float acc[2][8][4];
    #pragma unroll
    for (int mt = 0; mt < 2; mt++)
        #pragma unroll
        for (int nt = 0; nt < 8; nt++)
            #pragma unroll
            for (int c = 0; c < 4; c++) acc[mt][nt][c] = 0.f;

    auto load_stage = [&](int s, int k0) {
        CP_ASYNC_CG_Z(sA + (uint32_t)(s * 128 * LDA) * 4 + a_dst, a_src + k0, a_sz);
        CP_ASYNC_CG(sB + (uint32_t)(s * BK * LDB) * 4 + b_dst, b_src + (size_t)k0 * FDIM);
    };

    constexpr int NK = K / BK;
    #pragma unroll
    for (int s = 0; s < S - 1; s++) {
        load_stage(s, s * BK);
        CP_COMMIT();
    }

    int r0base = wm * 32 + gid;
    int jbase  = wn * 16 + (gid >> 2);
    int cl     = gid & 3;
    int sw     = tig << 1;

    for (int i = 0; i < NK; i++) {
        CP_WAIT2();
        __syncthreads();

        const float* as = As[i & (S - 1)];
        const float* bs = Bs[i & (S - 1)];

        uint32_t a[2][4], b[8][2];
        #pragma unroll
        for (int mt = 0; mt < 2; mt++) {
            int r = r0base + mt * 16;
            a[mt][0] = __float_as_uint(as[r * LDA + tig]);
            a[mt][1] = __float_as_uint(as[(r + 8) * LDA + tig]);
            a[mt][2] = __float_as_uint(as[r * LDA + tig + 4]);
            a[mt][3] = __float_as_uint(as[(r + 8) * LDA + tig + 4]);
        }
        #pragma unroll
        for (int nt = 0; nt < 8; nt++) {
            int j  = jbase + nt * 2;
            int w0 = ((j ^ sw) << 2) + cl;
            b[nt][0] = __float_as_uint(bs[tig * LDB + w0]);
            b[nt][1] = __float_as_uint(bs[(tig + 4) * LDB + w0]);
        }
        #pragma unroll
        for (int mt = 0; mt < 2; mt++)
            #pragma unroll
            for (int nt = 0; nt < 8; nt++) {
                asm volatile(
                    "mma.sync.aligned.m16n8k8.row.col.f32.tf32.tf32.f32 "
                    "{%0,%1,%2,%3}, {%4,%5,%6,%7}, {%8,%9}, {%0,%1,%2,%3};"
                    : "+f"(acc[mt][nt][0]), "+f"(acc[mt][nt][1]),
                      "+f"(acc[mt][nt][2]), "+f"(acc[mt][nt][3])
                    : "r"(a[mt][0]), "r"(a[mt][1]), "r"(a[mt][2]), "r"(a[mt][3]),
                      "r"(b[nt][0]), "r"(b[nt][1]));
            }

        int nx = i + S - 1;
        if (nx < NK) load_stage(nx & (S - 1), nx * BK);
        CP_COMMIT();
    }

    // ---- epilogue: bias add, bf16 pack, store ----
    #pragma unroll
    for (int mt = 0; mt < 2; mt++) {
        int row0 = rowBase + wm * 32 + mt * 16 + gid;
        int row1 = row0 + 8;
        #pragma unroll
        for (int nt = 0; nt < 8; nt++) {
            int col = colBase + wn * 64 + nt * 8 + tig * 2;
            float bx = bias[col], by = bias[col + 1];
            if (row0 < NN) {
                __nv_bfloat162 v0 = __floats2bfloat162_rn(acc[mt][nt][0] + bx,
                                                          acc[mt][nt][1] + by);
                *reinterpret_cast<__nv_bfloat162*>(out + (size_t)row0 * FDIM + col) = v0;
            }
            if (row1 < NN) {
                __nv_bfloat162 v1 = __floats2bfloat162_rn(acc[mt][nt][2] + bx,
                                                          acc[mt][nt][3] + by);
                *reinterpret_cast<__nv_bfloat162*>(out + (size_t)row1 * FDIM + col) = v1;
            }
        }
    }
}

// ---------------- fused edge logits + segment softmax + aggregation ----------
// One warp per dst node; xl/xr bf16. Lane l, iter k: head k*4+(l>>3),
// channels (l&7)*8..+8. Logit reduce: shfl 1,2,4; head-mean: shfl 8,16.
// Non-FINAL writes g_h pre-rounded to tf32 (for the layer-2 GEMM).
__device__ __forceinline__ float lrelu(float v, float s) {
    return v >= 0.f ? v : s * v;
}

__device__ __forceinline__ void bf8_to_f32(const uint4& u, float* f) {
    float2 p;
    p = __bfloat1622float2(*reinterpret_cast<const __nv_bfloat162*>(&u.x));
    f[0] = p.x; f[1] = p.y;
    p = __bfloat1622float2(*reinterpret_cast<const __nv_bfloat162*>(&u.y));
    f[2] = p.x; f[3] = p.y;
    p = __bfloat1622float2(*reinterpret_cast<const __nv_bfloat162*>(&u.z));
    f[4] = p.x; f[5] = p.y;
    p = __bfloat1622float2(*reinterpret_cast<const __nv_bfloat162*>(&u.w));
    f[6] = p.x; f[7] = p.y;
}

template <bool FINAL>
__global__ __launch_bounds__(256, 2) void edge_kernel(
    const float* __restrict__ att,    // [16*64]
    const float* __restrict__ bias,   // [64]
    const int*   __restrict__ batch)  // [NN] (FINAL only)
{
    __shared__ float att_s[FDIM];
    reinterpret_cast<float4*>(att_s)[threadIdx.x] =
        reinterpret_cast<const float4*>(att)[threadIdx.x];
    __syncthreads();

    int lane = threadIdx.x & 31;
    int warp = threadIdx.x >> 5;
    int n = blockIdx.x * 8 + warp;
    if (n >= NN) return;

    int beg = g_offs[n], end = g_offs[n + 1];
    int grp = lane >> 3, sub = lane & 7;

    const uint4* xlp = reinterpret_cast<const uint4*>(g_xl);
    const uint4* xrp = reinterpret_cast<const uint4*>(g_xr) + (size_t)n * 128;

    uint4 xr_raw[4];
    #pragma unroll
    for (int k = 0; k < 4; k++) xr_raw[k] = xrp[k * 32 + lane];

    float d[4], acc[4][8];
    #pragma unroll
    for (int k = 0; k < 4; k++) {
        d[k] = 0.f;
        #pragma unroll
        for (int j = 0; j < 8; j++) acc[k][j] = 0.f;
    }

    int e = beg;
    for (; e + 1 < end; e += 2) {
        int s0 = g_srcs[e], s1 = g_srcs[e + 1];
        const uint4* x0p = xlp + (size_t)s0 * 128;
        const uint4* x1p = xlp + (size_t)s1 * 128;
        uint4 xv0[4], xv1[4];
        #pragma unroll
        for (int k = 0; k < 4; k++) xv0[k] = x0p[k * 32 + lane];
        #pragma unroll
        for (int k = 0; k < 4; k++) xv1[k] = x1p[k * 32 + lane];

        #pragma unroll
        for (int k = 0; k < 4; k++) {
            float xr8[8], x0[8], x1[8];
            bf8_to_f32(xr_raw[k], xr8);
            bf8_to_f32(xv0[k], x0);
            bf8_to_f32(xv1[k], x1);
            const float* av = att_s + ((k * 4 + grp) * 64 + sub * 8);
            float l0 = 0.f, l1 = 0.f;
            #pragma unroll
            for (int j = 0; j < 8; j++) {
                float a = av[j];
                l0 += lrelu(x0[j] + xr8[j], 0.2f) * a;
                l1 += lrelu(x1[j] + xr8[j], 0.2f) * a;
            }
            #pragma unroll
            for (int o = 1; o <= 4; o <<= 1) {
                l0 += __shfl_xor_sync(0xffffffffu, l0, o);
                l1 += __shfl_xor_sync(0xffffffffu, l1, o);
            }
            float w0 = __expf(l0), w1 = __expf(l1);
            d[k] += w0 + w1;
            #pragma unroll
            for (int j = 0; j < 8; j++)
                acc[k][j] += w0 * x0[j] + w1 * x1[j];
        }
    }
    if (e < end) {
        int s0 = g_srcs[e];
        const uint4* x0p = xlp + (size_t)s0 * 128;
        uint4 xv0[4];
        #pragma unroll
        for (int k = 0; k < 4; k++) xv0[k] = x0p[k * 32 + lane];
        #pragma unroll
        for (int k = 0; k < 4; k++) {
            float xr8[8], x0[8];
            bf8_to_f32(xr_raw[k], xr8);
            bf8_to_f32(xv0[k], x0);
            const float* av = att_s + ((k * 4 + grp) * 64 + sub * 8);
            float l0 = 0.f;
            #pragma unroll
            for (int j = 0; j < 8; j++)
                l0 += lrelu(x0[j] + xr8[j], 0.2f) * av[j];
            #pragma unroll
            for (int o = 1; o <= 4; o <<= 1)
                l0 += __shfl_xor_sync(0xffffffffu, l0, o);
            float w0 = __expf(l0);
            d[k] += w0;
            #pragma unroll
            for (int j = 0; j < 8; j++)
                acc[k][j] += w0 * x0[j];
        }
    }

    float r[8];
    #pragma unroll
    for (int j = 0; j < 8; j++) r[j] = 0.f;
    #pragma unroll
    for (int k = 0; k < 4; k++) {
        float inv = 1.f / d[k];
        #pragma unroll
        for (int j = 0; j < 8; j++) r[j] += acc[k][j] * inv;
    }
    #pragma unroll
    for (int j = 0; j < 8; j++) {
        r[j] += __shfl_xor_sync(0xffffffffu, r[j], 8);
        r[j] += __shfl_xor_sync(0xffffffffu, r[j], 16);
    }

    if (lane < 8) {
        int c = lane * 8;
        const float inv16 = 1.f / 16.f;
        float o[8];
        #pragma unroll
        for (int j = 0; j < 8; j++)
            o[j] = lrelu(r[j] * inv16 + bias[c + j], 0.01f);
        if (FINAL) {
            int b = batch[n];
            #pragma unroll
            for (int j = 0; j < 8; j++)
                atomicAdd(&g_pool[b * HID + c + j], o[j]);
            if (lane == 0) atomicAdd(&g_pcnt[b], 1);
        } else {
            // pre-round to tf32 so the layer-2 GEMM needs no CVTs
            float4 v0, v1;
            v0.x = __uint_as_float(f2tf(o[0]));
            v0.y = __uint_as_float(f2tf(o[1]));
            v0.z = __uint_as_float(f2tf(o[2]));
            v0.w = __uint_as_float(f2tf(o[3]));
            v1.x = __uint_as_float(f2tf(o[4]));
            v1.y = __uint_as_float(f2tf(o[5]));
            v1.z = __uint_as_float(f2tf(o[6]));
            v1.w = __uint_as_float(f2tf(o[7]));
            *reinterpret_cast<float4*>(g_h + (size_t)n * HID + c)     = v0;
            *reinterpret_cast<float4*>(g_h + (size_t)n * HID + c + 4) = v1;
        }
    }
}

// ---------------- classifier/variance heads ----------------
__global__ void head_kernel(const float* __restrict__ Wc, const float* __restrict__ bc,
                            const float* __restrict__ Wv, const float* __restrict__ bv,
                            float* __restrict__ out) {
    __shared__ float p[HID];
    int b = blockIdx.x, c = threadIdx.x;
    float cnt = fmaxf((float)g_pcnt[b], 1.f);
    p[c] = g_pool[b * HID + c] / cnt;
    __syncthreads();
    if (c < 10) {
        float s = bc[c];
        #pragma unroll 8
        for (int k = 0; k < HID; k++) s += p[k] * Wc[k * 10 + c];
        out[b * 10 + c] = s;                 // logits [64,10]
    } else if (c == 10) {
        float s = bv[0];
        #pragma unroll 8
        for (int k = 0; k < HID; k++) s += p[k] * Wv[k];
        out[BB * 10 + b] = s;                // log_var [64,1]
    }
}

// ---------------- launch ----------------
extern "C" void kernel_launch(void* const* d_in, const int* in_sizes, int n_in,
                              void* d_out, int out_size) {
    const float* x     = (const float*)d_in[0];
    const int*   ei    = (const int*)  d_in[1];
    const int*   batch = (const int*)  d_in[2];
    const float* W1l   = (const float*)d_in[3];
    const float* b1l   = (const float*)d_in[4];
    const float* W1r   = (const float*)d_in[5];
    const float* b1r   = (const float*)d_in[6];
    const float* att1  = (const float*)d_in[7];
    const float* bias1 = (const float*)d_in[8];
    const float* W2l   = (const float*)d_in[9];
    const float* b2l   = (const float*)d_in[10];
    const float* W2r   = (const float*)d_in[11];
    const float* b2r   = (const float*)d_in[12];
    const float* att2  = (const float*)d_in[13];
    const float* bias2 = (const float*)d_in[14];
    const float* Wc    = (const float*)d_in[15];
    const float* bc    = (const float*)d_in[16];
    const float* Wv    = (const float*)d_in[17];
    const float* bv    = (const float*)d_in[18];
    float* out = (float*)d_out;

    zero_kernel<<<(NN + 255) / 256, 256>>>();
    hist_kernel<<<(ETOT + 255) / 256, 256>>>(ei);
    scan_kernel<<<1, 1024>>>();
    scatter_kernel<<<(ETOT + 255) / 256, 256>>>(ei);

    // pre-round operands to tf32 (RNA) once
    round_x_kernel<<<(NN * 128 / 4 + 255) / 256, 256>>>(x);
    round_w_kernel<1><<<(128 * FDIM / 4 + 255) / 256, 256>>>(W1l, W1r);
    round_w_kernel<2><<<(64 * FDIM / 4 + 255) / 256, 256>>>(W2l, W2r);

    dim3 ggrid((NN + 127) / 128, FDIM / 128, 2);

    gemm_tc_kernel<128, 1><<<ggrid, 256>>>(b1l, b1r);
    edge_kernel<false><<<(NN + 7) / 8, 256>>>(att1, bias1, batch);

    gemm_tc_kernel<64, 2><<<ggrid, 256>>>(b2l, b2r);
    edge_kernel<true><<<(NN + 7) / 8, 256>>>(att2, bias2, batch);

    head_kernel<<<BB, HID>>>(Wc, bc, Wv, bv, out);
}